// round 8
// baseline (speedup 1.0000x reference)
#include <cuda_runtime.h>
#include <cuda_bf16.h>
#include <cstdint>
#include <math.h>

#define B_SZ 16384
#define SCENE 256
#define FEAT 256
#define HID 1024
#define NSLOTS 8
typedef __nv_bfloat16 bf16;

// ---------------- device scratch ---------------------------------------------
// gates weights packed: row = ny*256 + wn*64 + hcg*32 + gate*8 + h8 ; K = 1280
// (hidden unit = ny*64 + wn*16 + hcg*8 + h8, ny in [0,16), wn in [0,4))
__device__ bf16 g_Wg_hi[4096 * 1280];
__device__ bf16 g_Wg_lo[4096 * 1280];
// heads weights packed: row = nb*256 + wn*64 + hcg*16 + head*8 + h8 ; K = 1024
// (feature = nb*128 + wn*32 + hcg*8 + h8, nb in [0,2))
__device__ bf16 g_Wo_hi[512 * 1024];
__device__ bf16 g_Wo_lo[512 * 1024];
__device__ bf16 g_x_hi[B_SZ * FEAT];
__device__ bf16 g_x_lo[B_SZ * FEAT];
__device__ bf16 g_hA_hi[B_SZ * HID];
__device__ bf16 g_hA_lo[B_SZ * HID];
__device__ bf16 g_hB_hi[B_SZ * HID];
__device__ bf16 g_hB_lo[B_SZ * HID];
__device__ float g_c[B_SZ * HID];

// ---------------- helpers -----------------------------------------------------
__device__ __forceinline__ uint32_t s2u(const void* p) {
    uint32_t a;
    asm("{.reg .u64 t; cvta.to.shared.u64 t,%1; cvt.u32.u64 %0,t;}" : "=r"(a) : "l"(p));
    return a;
}
#define CP16(dst, src) asm volatile("cp.async.cg.shared.global [%0], [%1], 16;" ::"r"(dst), "l"(src))
#define CPCOMMIT() asm volatile("cp.async.commit_group;" ::: "memory")
#define CPWAIT1() asm volatile("cp.async.wait_group 1;" ::: "memory")

__device__ __forceinline__ void ldsm4(uint32_t* r, uint32_t a) {
    asm volatile("ldmatrix.sync.aligned.m8n8.x4.shared.b16 {%0,%1,%2,%3},[%4];"
                 : "=r"(r[0]), "=r"(r[1]), "=r"(r[2]), "=r"(r[3]) : "r"(a));
}
__device__ __forceinline__ void mma16816(float* c, const uint32_t* a, const uint32_t* b) {
    asm volatile("mma.sync.aligned.m16n8k16.row.col.f32.bf16.bf16.f32 "
                 "{%0,%1,%2,%3},{%4,%5,%6,%7},{%8,%9},{%0,%1,%2,%3};"
                 : "+f"(c[0]), "+f"(c[1]), "+f"(c[2]), "+f"(c[3])
                 : "r"(a[0]), "r"(a[1]), "r"(a[2]), "r"(a[3]), "r"(b[0]), "r"(b[1]));
}

__device__ __forceinline__ float sig_(float x) { return 1.f / (1.f + __expf(-x)); }
__device__ __forceinline__ float tanh_(float x) { return 2.f * sig_(2.f * x) - 1.f; }
__device__ __forceinline__ float sp_(float x) { return fmaxf(x, 0.f) + __logf(1.f + __expf(-fabsf(x))); }
__device__ __forceinline__ void splt(float v, bf16& h, bf16& l) {
    h = __float2bfloat16(v); l = __float2bfloat16(v - __bfloat162float(h));
}

// ---------------- smem layout ---------------------------------------------------
// per stage (k32 chunk, 256x256 tile): A_hi | A_lo | B_hi | B_lo, each 256 rows x 80B
#define SUB 20480
#define OFF_ALO SUB
#define OFF_BHI (2 * SUB)
#define OFF_BLO (3 * SUB)
#define STG (4 * SUB)               // 81920
#define OFF_BIAS (2 * STG)          // 163840
#define SMEM_T (OFF_BIAS + 1024)    // 164864 -> 1 CTA/SM, 16 warps

// ---------------- fused chunk loader (hi+lo, A+B), 512 threads -------------------
__device__ __forceinline__ void load_chunk(uint32_t stg,
                                           const bf16* __restrict__ aHi, const bf16* __restrict__ aLo, int aK,
                                           const bf16* __restrict__ bHi, const bf16* __restrict__ bLo, int bK,
                                           int tid) {
#pragma unroll
    for (int q = 0; q < 2; ++q) {
        const int idx = tid + q * 512;      // 1024 lines per region: 256 rows x 4 chunks
        const int r = idx >> 2, ch = idx & 3;
        CP16(stg + r * 80 + ch * 16,           (const char*)(aHi + (size_t)r * aK) + ch * 16);
        CP16(stg + OFF_ALO + r * 80 + ch * 16, (const char*)(aLo + (size_t)r * aK) + ch * 16);
        CP16(stg + OFF_BHI + r * 80 + ch * 16, (const char*)(bHi + (size_t)r * bK) + ch * 16);
        CP16(stg + OFF_BLO + r * 80 + ch * 16, (const char*)(bLo + (size_t)r * bK) + ch * 16);
    }
}

// ---------------- compute one fused k32 chunk (3 split terms) --------------------
// 16 warps: wm in [0,4) (M64), wn in [0,4) (N64); warp tile 64x64
__device__ __forceinline__ void compute_chunk(uint32_t sa, float acc[4][8][4],
                                              int wm, int wn, int lane) {
#pragma unroll
    for (int kk = 0; kk < 2; ++kk) {
        uint32_t ahi[4][4], alo[4][4];
#pragma unroll
        for (int i = 0; i < 4; ++i) {
            const int row = wm * 64 + i * 16 + (lane & 15);
            const uint32_t off = row * 80 + kk * 32 + ((lane >> 4) << 4);
            ldsm4(ahi[i], sa + off);
            ldsm4(alo[i], sa + OFF_ALO + off);
        }
#pragma unroll
        for (int jp = 0; jp < 4; ++jp) {
            const int brow = wn * 64 + jp * 16 + ((lane & 7) | ((lane >> 4) << 3));
            const uint32_t boff = brow * 80 + kk * 32 + (((lane >> 3) & 1) << 4);
            uint32_t bh[4], bl[4];
            ldsm4(bh, sa + OFF_BHI + boff);
#pragma unroll
            for (int i = 0; i < 4; ++i) {
                mma16816(acc[i][jp * 2 + 0], ahi[i], &bh[0]);
                mma16816(acc[i][jp * 2 + 1], ahi[i], &bh[2]);
            }
#pragma unroll
            for (int i = 0; i < 4; ++i) {
                mma16816(acc[i][jp * 2 + 0], alo[i], &bh[0]);
                mma16816(acc[i][jp * 2 + 1], alo[i], &bh[2]);
            }
            ldsm4(bl, sa + OFF_BLO + boff);
#pragma unroll
            for (int i = 0; i < 4; ++i) {
                mma16816(acc[i][jp * 2 + 0], ahi[i], &bl[0]);
                mma16816(acc[i][jp * 2 + 1], ahi[i], &bl[2]);
            }
        }
    }
}

// ---------------- weight repack ---------------------------------------------------
__global__ void conv_weights(const float* __restrict__ Wih, const float* __restrict__ Whh,
                             const float* __restrict__ Wmu, const float* __restrict__ Wsp) {
    int i = blockIdx.x * 256 + threadIdx.x;
    const int NG = 4096 * 1280;
    if (i < NG) {
        int r = i / 1280, k = i - r * 1280;
        int ny = r >> 8, w = r & 255;
        int wn = w >> 6, hcg = (w >> 5) & 1, gate = (w >> 3) & 3, h8 = w & 7;
        int hidden = ny * 64 + wn * 16 + hcg * 8 + h8;
        int o = gate * HID + hidden;
        float v = (k < FEAT) ? Wih[(size_t)o * FEAT + k] : Whh[(size_t)o * HID + (k - FEAT)];
        splt(v, g_Wg_hi[i], g_Wg_lo[i]);
    } else {
        int j = i - NG;
        if (j < 512 * 1024) {
            int r = j / 1024, k = j - r * 1024;
            int nb = r >> 8, w = r & 255;
            int wn = w >> 6, hcg = (w >> 4) & 3, head = (w >> 3) & 1, h8 = w & 7;
            int f = nb * 128 + wn * 32 + hcg * 8 + h8;
            float v = head ? Wsp[(size_t)f * HID + k] : Wmu[(size_t)f * HID + k];
            splt(v, g_Wo_hi[j], g_Wo_lo[j]);
        }
    }
}

// ---------------- encoder (SIMT fp32) ----------------------------------------------
__global__ void __launch_bounds__(256, 2) enc_kernel(const float* __restrict__ S,
                                                     const float* __restrict__ We,
                                                     const float* __restrict__ be) {
    __shared__ float As[16 * 65], Ws[16 * 33];
    const int tid = threadIdx.x, tx = tid & 15, ty = tid >> 4;
    const int m0 = blockIdx.x * 64, n0 = blockIdx.y * 32;
    float acc[8];
#pragma unroll
    for (int i = 0; i < 8; ++i) acc[i] = 0.f;
    const int rl = tid >> 2, kl = (tid & 3) * 4;
    for (int k0 = 0; k0 < SCENE; k0 += 16) {
        float4 v = *reinterpret_cast<const float4*>(&S[(size_t)(m0 + rl) * SCENE + k0 + kl]);
        As[(kl + 0) * 65 + rl] = v.x; As[(kl + 1) * 65 + rl] = v.y;
        As[(kl + 2) * 65 + rl] = v.z; As[(kl + 3) * 65 + rl] = v.w;
        if (tid < 128) {
            int c = tid >> 2, kc = (tid & 3) * 4;
            float4 w = *reinterpret_cast<const float4*>(&We[(size_t)(n0 + c) * SCENE + k0 + kc]);
            Ws[(kc + 0) * 33 + c] = w.x; Ws[(kc + 1) * 33 + c] = w.y;
            Ws[(kc + 2) * 33 + c] = w.z; Ws[(kc + 3) * 33 + c] = w.w;
        }
        __syncthreads();
#pragma unroll
        for (int k = 0; k < 16; ++k) {
            float a0 = As[k * 65 + ty * 4], a1 = As[k * 65 + ty * 4 + 1];
            float a2 = As[k * 65 + ty * 4 + 2], a3 = As[k * 65 + ty * 4 + 3];
            float w0 = Ws[k * 33 + tx * 2], w1 = Ws[k * 33 + tx * 2 + 1];
            acc[0] = fmaf(a0, w0, acc[0]); acc[1] = fmaf(a0, w1, acc[1]);
            acc[2] = fmaf(a1, w0, acc[2]); acc[3] = fmaf(a1, w1, acc[3]);
            acc[4] = fmaf(a2, w0, acc[4]); acc[5] = fmaf(a2, w1, acc[5]);
            acc[6] = fmaf(a3, w0, acc[6]); acc[7] = fmaf(a3, w1, acc[7]);
        }
        __syncthreads();
    }
#pragma unroll
    for (int c = 0; c < 2; ++c) {
        const int col = n0 + tx * 2 + c;
        const float b = be[col];
#pragma unroll
        for (int r = 0; r < 4; ++r) {
            const int row = m0 + ty * 4 + r;
            float v = acc[r * 2 + c] + b;
            v = 0.5f * v * (1.f + erff(v * 0.7071067811865476f));
            splt(v, g_x_hi[(size_t)row * FEAT + col], g_x_lo[(size_t)row * FEAT + col]);
        }
    }
}

// ---------------- gates GEMM + in-register LSTM cell --------------------------------
template <bool FIRST>
__global__ void __launch_bounds__(512, 1) gates_mma(int t, const float* __restrict__ bih,
                                                    const float* __restrict__ bhh) {
    extern __shared__ char sm[];
    const uint32_t smu = s2u(sm);
    const int tid = threadIdx.x, lane = tid & 31, wid = tid >> 5;
    const int wm = wid >> 2, wn = wid & 3;
    const int m0 = blockIdx.x * 256, ny = blockIdx.y;

    const bf16* hp_hi = (t & 1) ? g_hA_hi : g_hB_hi;
    const bf16* hp_lo = (t & 1) ? g_hA_lo : g_hB_lo;
    bf16* ho_hi = (t & 1) ? g_hB_hi : g_hA_hi;
    bf16* ho_lo = (t & 1) ? g_hB_lo : g_hA_lo;

    float* bs = reinterpret_cast<float*>(sm + OFF_BIAS);
    if (tid < 256) {
        int wn2 = tid >> 6, hcg = (tid >> 5) & 1, gate = (tid >> 3) & 3, h8 = tid & 7;
        int hidden = ny * 64 + wn2 * 16 + hcg * 8 + h8;
        bs[tid] = bih[gate * HID + hidden] + bhh[gate * HID + hidden];
    }

    const int NC = FIRST ? 8 : 40;
    float acc[4][8][4];
#pragma unroll
    for (int i = 0; i < 4; ++i)
#pragma unroll
        for (int j = 0; j < 8; ++j)
#pragma unroll
            for (int e = 0; e < 4; ++e) acc[i][j][e] = 0.f;

    auto issue_load = [&](int cs) {
        const int kc = cs * 32;
        const bf16 *aH, *aL; int aK;
        if (FIRST || kc < 256) {
            aH = g_x_hi + (size_t)m0 * FEAT + kc;
            aL = g_x_lo + (size_t)m0 * FEAT + kc; aK = FEAT;
        } else {
            aH = hp_hi + (size_t)m0 * HID + (kc - 256);
            aL = hp_lo + (size_t)m0 * HID + (kc - 256); aK = HID;
        }
        const size_t bo = (size_t)(ny * 256) * 1280 + kc;
        load_chunk(smu + (cs & 1) * STG, aH, aL, aK, g_Wg_hi + bo, g_Wg_lo + bo, 1280, tid);
        CPCOMMIT();
    };

    issue_load(0); issue_load(1);
    for (int cs = 0; cs < NC; ++cs) {
        CPWAIT1();
        __syncthreads();
        compute_chunk(smu + (cs & 1) * STG, acc, wm, wn, lane);
        __syncthreads();
        if (cs + 2 < NC) issue_load(cs + 2); else CPCOMMIT();
    }

    // in-register LSTM cell epilogue: acc col j = hcg*4 + gate
    const int lane4 = lane >> 2, lq = lane & 3;
#pragma unroll
    for (int i = 0; i < 4; ++i)
#pragma unroll
        for (int rp = 0; rp < 2; ++rp) {
            const int row = m0 + wm * 64 + i * 16 + lane4 + rp * 8;
#pragma unroll
            for (int hcg = 0; hcg < 2; ++hcg) {
                const int h8b = lq * 2;
                const int hidden = ny * 64 + wn * 16 + hcg * 8 + h8b;
                const size_t base = (size_t)row * HID + hidden;
                const int bb = wn * 64 + hcg * 32 + h8b;
                float2 cold = make_float2(0.f, 0.f);
                if (!FIRST) cold = *reinterpret_cast<const float2*>(&g_c[base]);
                float cn[2];
                union { bf16 b[2]; uint32_t u; } Hh, Hl;
#pragma unroll
                for (int eb = 0; eb < 2; ++eb) {
                    const int e = rp * 2 + eb;
                    const float gi = acc[i][hcg * 4 + 0][e] + bs[bb + 0 + eb];
                    const float gf = acc[i][hcg * 4 + 1][e] + bs[bb + 8 + eb];
                    const float gg = acc[i][hcg * 4 + 2][e] + bs[bb + 16 + eb];
                    const float go = acc[i][hcg * 4 + 3][e] + bs[bb + 24 + eb];
                    const float cp = FIRST ? 0.f : (eb ? cold.y : cold.x);
                    const float c2 = sig_(gf) * cp + sig_(gi) * tanh_(gg);
                    cn[eb] = c2;
                    splt(sig_(go) * tanh_(c2), Hh.b[eb], Hl.b[eb]);
                }
                *reinterpret_cast<float2*>(&g_c[base]) = make_float2(cn[0], cn[1]);
                *reinterpret_cast<uint32_t*>(&ho_hi[base]) = Hh.u;
                *reinterpret_cast<uint32_t*>(&ho_lo[base]) = Hl.u;
            }
        }
}

// ---------------- heads GEMM: mu | softplus sigma | z --------------------------------
__global__ void __launch_bounds__(512, 1) heads_mma(int t, const float* __restrict__ bmu,
                                                    const float* __restrict__ bsp,
                                                    const float* __restrict__ eps,
                                                    float* __restrict__ zs,
                                                    float* __restrict__ mus,
                                                    float* __restrict__ sgs) {
    extern __shared__ char sm[];
    const uint32_t smu = s2u(sm);
    const int tid = threadIdx.x, lane = tid & 31, wid = tid >> 5;
    const int wm = wid >> 2, wn = wid & 3;
    const int m0 = blockIdx.x * 256, nb = blockIdx.y;

    const bf16* hc_hi = (t & 1) ? g_hB_hi : g_hA_hi;
    const bf16* hc_lo = (t & 1) ? g_hB_lo : g_hA_lo;

    float* bs = reinterpret_cast<float*>(sm + OFF_BIAS);
    if (tid < 256) {
        int wn2 = tid >> 6, hcg = (tid >> 4) & 3, head = (tid >> 3) & 1, h8 = tid & 7;
        int f = nb * 128 + wn2 * 32 + hcg * 8 + h8;
        bs[tid] = head ? bsp[f] : bmu[f];
    }

    const int NC = 32;
    float acc[4][8][4];
#pragma unroll
    for (int i = 0; i < 4; ++i)
#pragma unroll
        for (int j = 0; j < 8; ++j)
#pragma unroll
            for (int e = 0; e < 4; ++e) acc[i][j][e] = 0.f;

    auto issue_load = [&](int cs) {
        const int kc = cs * 32;
        const bf16* aH = hc_hi + (size_t)m0 * HID + kc;
        const bf16* aL = hc_lo + (size_t)m0 * HID + kc;
        const size_t bo = (size_t)(nb * 256) * 1024 + kc;
        load_chunk(smu + (cs & 1) * STG, aH, aL, HID, g_Wo_hi + bo, g_Wo_lo + bo, 1024, tid);
        CPCOMMIT();
    };

    issue_load(0); issue_load(1);
    for (int cs = 0; cs < NC; ++cs) {
        CPWAIT1();
        __syncthreads();
        compute_chunk(smu + (cs & 1) * STG, acc, wm, wn, lane);
        __syncthreads();
        if (cs + 2 < NC) issue_load(cs + 2); else CPCOMMIT();
    }

    // in-register heads epilogue: acc col j = hcg*2 + head
    const int lane4 = lane >> 2, lq = lane & 3;
#pragma unroll
    for (int i = 0; i < 4; ++i)
#pragma unroll
        for (int rp = 0; rp < 2; ++rp) {
            const int row = m0 + wm * 64 + i * 16 + lane4 + rp * 8;
#pragma unroll
            for (int hcg = 0; hcg < 4; ++hcg) {
                const int h8b = lq * 2;
                const int f = nb * 128 + wn * 32 + hcg * 8 + h8b;
                const size_t o = (size_t)t * B_SZ * FEAT + (size_t)row * FEAT + f;
                const size_t xb = (size_t)row * FEAT + f;
                const int bb = wn * 64 + hcg * 16 + h8b;
                const float2 ev = *reinterpret_cast<const float2*>(&eps[o]);
                float zv[2], mv[2], sv[2];
                union { bf16 b[2]; uint32_t u; } Zh, Zl;
#pragma unroll
                for (int eb = 0; eb < 2; ++eb) {
                    const int e = rp * 2 + eb;
                    const float mu = acc[i][hcg * 2 + 0][e] + bs[bb + 0 + eb];
                    const float sg = sp_(acc[i][hcg * 2 + 1][e] + bs[bb + 8 + eb]);
                    const float z = mu + sg * (eb ? ev.y : ev.x);
                    mv[eb] = mu; sv[eb] = sg; zv[eb] = z;
                    splt(z, Zh.b[eb], Zl.b[eb]);
                }
                *reinterpret_cast<float2*>(&zs[o])  = make_float2(zv[0], zv[1]);
                *reinterpret_cast<float2*>(&mus[o]) = make_float2(mv[0], mv[1]);
                *reinterpret_cast<float2*>(&sgs[o]) = make_float2(sv[0], sv[1]);
                *reinterpret_cast<uint32_t*>(&g_x_hi[xb]) = Zh.u;
                *reinterpret_cast<uint32_t*>(&g_x_lo[xb]) = Zl.u;
            }
        }
}

// ---------------- launch --------------------------------------------------------------
extern "C" void kernel_launch(void* const* d_in, const int* in_sizes, int n_in,
                              void* d_out, int out_size) {
    (void)in_sizes; (void)n_in; (void)out_size;
    const float* S   = (const float*)d_in[0];
    const float* eps = (const float*)d_in[1];
    const float* We  = (const float*)d_in[3];
    const float* be  = (const float*)d_in[4];
    const float* Wih = (const float*)d_in[5];
    const float* Whh = (const float*)d_in[6];
    const float* bih = (const float*)d_in[7];
    const float* bhh = (const float*)d_in[8];
    const float* Wmu = (const float*)d_in[9];
    const float* bmu = (const float*)d_in[10];
    const float* Wsp = (const float*)d_in[11];
    const float* bsp = (const float*)d_in[12];

    float* out = (float*)d_out;
    const size_t slab = (size_t)NSLOTS * B_SZ * FEAT;
    float *zs = out, *mus = out + slab, *sgs = out + 2 * slab;

    static bool attr_done = false;
    if (!attr_done) {
        cudaFuncSetAttribute(gates_mma<true>,  cudaFuncAttributeMaxDynamicSharedMemorySize, SMEM_T);
        cudaFuncSetAttribute(gates_mma<false>, cudaFuncAttributeMaxDynamicSharedMemorySize, SMEM_T);
        cudaFuncSetAttribute(heads_mma,        cudaFuncAttributeMaxDynamicSharedMemorySize, SMEM_T);
        attr_done = true;
    }

    conv_weights<<<22528, 256>>>(Wih, Whh, Wmu, Wsp);
    enc_kernel<<<dim3(B_SZ / 64, FEAT / 32), 256>>>(S, We, be);

    for (int t = 0; t < NSLOTS; ++t) {
        if (t == 0)
            gates_mma<true><<<dim3(B_SZ / 256, 16), 512, SMEM_T>>>(t, bih, bhh);
        else
            gates_mma<false><<<dim3(B_SZ / 256, 16), 512, SMEM_T>>>(t, bih, bhh);
        heads_mma<<<dim3(B_SZ / 256, 2), 512, SMEM_T>>>(t, bmu, bsp, eps, zs, mus, sgs);
    }
}

// round 12
// speedup vs baseline: 1.7308x; 1.7308x over previous
#include <cuda_runtime.h>
#include <cuda_bf16.h>
#include <cstdint>
#include <math.h>

#define B_SZ 16384
#define SCENE 256
#define FEAT 256
#define HID 1024
#define NSLOTS 8
typedef __nv_bfloat16 bf16;

// ---------------- device scratch ---------------------------------------------
// gates weights packed: row = ny*256 + wn*64 + hcg*32 + gate*8 + h8 ; K = 1280
// (hidden unit = ny*64 + wn*16 + hcg*8 + h8, ny in [0,16), wn in [0,4))
__device__ bf16 g_Wg_hi[4096 * 1280];
__device__ bf16 g_Wg_lo[4096 * 1280];
// heads weights packed: row = nb*256 + wn*64 + hcg*16 + head*8 + h8 ; K = 1024
// (feature = nb*128 + wn*32 + hcg*8 + h8, nb in [0,2))
__device__ bf16 g_Wo_hi[512 * 1024];
__device__ bf16 g_Wo_lo[512 * 1024];
__device__ bf16 g_x_hi[B_SZ * FEAT];
__device__ bf16 g_x_lo[B_SZ * FEAT];
__device__ bf16 g_hA_hi[B_SZ * HID];
__device__ bf16 g_hA_lo[B_SZ * HID];
__device__ bf16 g_hB_hi[B_SZ * HID];
__device__ bf16 g_hB_lo[B_SZ * HID];
__device__ float g_c[B_SZ * HID];

// ---------------- helpers -----------------------------------------------------
__device__ __forceinline__ uint32_t s2u(const void* p) {
    uint32_t a;
    asm("{.reg .u64 t; cvta.to.shared.u64 t,%1; cvt.u32.u64 %0,t;}" : "=r"(a) : "l"(p));
    return a;
}
#define CP16(dst, src) asm volatile("cp.async.cg.shared.global [%0], [%1], 16;" ::"r"(dst), "l"(src))
#define CPCOMMIT() asm volatile("cp.async.commit_group;" ::: "memory")
#define CPWAIT2() asm volatile("cp.async.wait_group 2;" ::: "memory")

__device__ __forceinline__ void ldsm4(uint32_t* r, uint32_t a) {
    asm volatile("ldmatrix.sync.aligned.m8n8.x4.shared.b16 {%0,%1,%2,%3},[%4];"
                 : "=r"(r[0]), "=r"(r[1]), "=r"(r[2]), "=r"(r[3]) : "r"(a));
}
__device__ __forceinline__ void mma16816(float* c, const uint32_t* a, const uint32_t* b) {
    asm volatile("mma.sync.aligned.m16n8k16.row.col.f32.bf16.bf16.f32 "
                 "{%0,%1,%2,%3},{%4,%5,%6,%7},{%8,%9},{%0,%1,%2,%3};"
                 : "+f"(c[0]), "+f"(c[1]), "+f"(c[2]), "+f"(c[3])
                 : "r"(a[0]), "r"(a[1]), "r"(a[2]), "r"(a[3]), "r"(b[0]), "r"(b[1]));
}

__device__ __forceinline__ float sig_(float x) { return 1.f / (1.f + __expf(-x)); }
__device__ __forceinline__ float tanh_(float x) { return 2.f * sig_(2.f * x) - 1.f; }
__device__ __forceinline__ float sp_(float x) { return fmaxf(x, 0.f) + __logf(1.f + __expf(-fabsf(x))); }
__device__ __forceinline__ void splt(float v, bf16& h, bf16& l) {
    h = __float2bfloat16(v); l = __float2bfloat16(v - __bfloat162float(h));
}

// ---------------- smem layout ---------------------------------------------------
// per stage (k32 chunk, 128x256 tile): A_hi | A_lo (128 rows x 80B), B_hi | B_lo (256 rows x 80B)
#define A_SUB 10240
#define OFF_ALO A_SUB
#define OFF_BHI (2 * A_SUB)                  // 20480
#define OFF_BLO (2 * A_SUB + 20480)          // 40960
#define STG 61440
#define OFF_BIAS (3 * STG)                   // 184320
#define SMEM_T (OFF_BIAS + 1024)             // 185344 -> 1 CTA/SM, 8 warps, 255-reg cap

// ---------------- fused chunk loader (hi+lo, A+B), 256 threads -------------------
__device__ __forceinline__ void load_chunk(uint32_t stg,
                                           const bf16* __restrict__ aHi, const bf16* __restrict__ aLo, int aK,
                                           const bf16* __restrict__ bHi, const bf16* __restrict__ bLo, int bK,
                                           int tid) {
#pragma unroll
    for (int q = 0; q < 2; ++q) {              // A: 512 lines (128 rows x 4 chunks)
        const int idx = tid + q * 256;
        const int r = idx >> 2, ch = idx & 3;
        CP16(stg + r * 80 + ch * 16,           (const char*)(aHi + (size_t)r * aK) + ch * 16);
        CP16(stg + OFF_ALO + r * 80 + ch * 16, (const char*)(aLo + (size_t)r * aK) + ch * 16);
    }
#pragma unroll
    for (int q = 0; q < 4; ++q) {              // B: 1024 lines (256 rows x 4 chunks)
        const int idx = tid + q * 256;
        const int r = idx >> 2, ch = idx & 3;
        CP16(stg + OFF_BHI + r * 80 + ch * 16, (const char*)(bHi + (size_t)r * bK) + ch * 16);
        CP16(stg + OFF_BLO + r * 80 + ch * 16, (const char*)(bLo + (size_t)r * bK) + ch * 16);
    }
}

// ---------------- compute one fused k32 chunk (3 split terms) --------------------
// 8 warps: wm in [0,2) (M64), wn in [0,4) (N64); warp tile 64x64
__device__ __forceinline__ void compute_chunk(uint32_t sa, float acc[4][8][4],
                                              int wm, int wn, int lane) {
#pragma unroll
    for (int kk = 0; kk < 2; ++kk) {
        uint32_t ahi[4][4], alo[4][4];
#pragma unroll
        for (int i = 0; i < 4; ++i) {
            const int row = wm * 64 + i * 16 + (lane & 15);
            const uint32_t off = row * 80 + kk * 32 + ((lane >> 4) << 4);
            ldsm4(ahi[i], sa + off);
            ldsm4(alo[i], sa + OFF_ALO + off);
        }
#pragma unroll
        for (int jp = 0; jp < 4; ++jp) {
            const int brow = wn * 64 + jp * 16 + ((lane & 7) | ((lane >> 4) << 3));
            const uint32_t boff = brow * 80 + kk * 32 + (((lane >> 3) & 1) << 4);
            uint32_t bh[4], bl[4];
            ldsm4(bh, sa + OFF_BHI + boff);
#pragma unroll
            for (int i = 0; i < 4; ++i) {
                mma16816(acc[i][jp * 2 + 0], ahi[i], &bh[0]);
                mma16816(acc[i][jp * 2 + 1], ahi[i], &bh[2]);
            }
            ldsm4(bl, sa + OFF_BLO + boff);
#pragma unroll
            for (int i = 0; i < 4; ++i) {
                mma16816(acc[i][jp * 2 + 0], alo[i], &bh[0]);
                mma16816(acc[i][jp * 2 + 1], alo[i], &bh[2]);
            }
#pragma unroll
            for (int i = 0; i < 4; ++i) {
                mma16816(acc[i][jp * 2 + 0], ahi[i], &bl[0]);
                mma16816(acc[i][jp * 2 + 1], ahi[i], &bl[2]);
            }
        }
    }
}

// ---------------- weight repack ---------------------------------------------------
__global__ void conv_weights(const float* __restrict__ Wih, const float* __restrict__ Whh,
                             const float* __restrict__ Wmu, const float* __restrict__ Wsp) {
    int i = blockIdx.x * 256 + threadIdx.x;
    const int NG = 4096 * 1280;
    if (i < NG) {
        int r = i / 1280, k = i - r * 1280;
        int ny = r >> 8, w = r & 255;
        int wn = w >> 6, hcg = (w >> 5) & 1, gate = (w >> 3) & 3, h8 = w & 7;
        int hidden = ny * 64 + wn * 16 + hcg * 8 + h8;
        int o = gate * HID + hidden;
        float v = (k < FEAT) ? Wih[(size_t)o * FEAT + k] : Whh[(size_t)o * HID + (k - FEAT)];
        splt(v, g_Wg_hi[i], g_Wg_lo[i]);
    } else {
        int j = i - NG;
        if (j < 512 * 1024) {
            int r = j / 1024, k = j - r * 1024;
            int nb = r >> 8, w = r & 255;
            int wn = w >> 6, hcg = (w >> 4) & 3, head = (w >> 3) & 1, h8 = w & 7;
            int f = nb * 128 + wn * 32 + hcg * 8 + h8;
            float v = head ? Wsp[(size_t)f * HID + k] : Wmu[(size_t)f * HID + k];
            splt(v, g_Wo_hi[j], g_Wo_lo[j]);
        }
    }
}

// ---------------- encoder (SIMT fp32) ----------------------------------------------
__global__ void __launch_bounds__(256, 2) enc_kernel(const float* __restrict__ S,
                                                     const float* __restrict__ We,
                                                     const float* __restrict__ be) {
    __shared__ float As[16 * 65], Ws[16 * 33];
    const int tid = threadIdx.x, tx = tid & 15, ty = tid >> 4;
    const int m0 = blockIdx.x * 64, n0 = blockIdx.y * 32;
    float acc[8];
#pragma unroll
    for (int i = 0; i < 8; ++i) acc[i] = 0.f;
    const int rl = tid >> 2, kl = (tid & 3) * 4;
    for (int k0 = 0; k0 < SCENE; k0 += 16) {
        float4 v = *reinterpret_cast<const float4*>(&S[(size_t)(m0 + rl) * SCENE + k0 + kl]);
        As[(kl + 0) * 65 + rl] = v.x; As[(kl + 1) * 65 + rl] = v.y;
        As[(kl + 2) * 65 + rl] = v.z; As[(kl + 3) * 65 + rl] = v.w;
        if (tid < 128) {
            int c = tid >> 2, kc = (tid & 3) * 4;
            float4 w = *reinterpret_cast<const float4*>(&We[(size_t)(n0 + c) * SCENE + k0 + kc]);
            Ws[(kc + 0) * 33 + c] = w.x; Ws[(kc + 1) * 33 + c] = w.y;
            Ws[(kc + 2) * 33 + c] = w.z; Ws[(kc + 3) * 33 + c] = w.w;
        }
        __syncthreads();
#pragma unroll
        for (int k = 0; k < 16; ++k) {
            float a0 = As[k * 65 + ty * 4], a1 = As[k * 65 + ty * 4 + 1];
            float a2 = As[k * 65 + ty * 4 + 2], a3 = As[k * 65 + ty * 4 + 3];
            float w0 = Ws[k * 33 + tx * 2], w1 = Ws[k * 33 + tx * 2 + 1];
            acc[0] = fmaf(a0, w0, acc[0]); acc[1] = fmaf(a0, w1, acc[1]);
            acc[2] = fmaf(a1, w0, acc[2]); acc[3] = fmaf(a1, w1, acc[3]);
            acc[4] = fmaf(a2, w0, acc[4]); acc[5] = fmaf(a2, w1, acc[5]);
            acc[6] = fmaf(a3, w0, acc[6]); acc[7] = fmaf(a3, w1, acc[7]);
        }
        __syncthreads();
    }
#pragma unroll
    for (int c = 0; c < 2; ++c) {
        const int col = n0 + tx * 2 + c;
        const float b = be[col];
#pragma unroll
        for (int r = 0; r < 4; ++r) {
            const int row = m0 + ty * 4 + r;
            float v = acc[r * 2 + c] + b;
            v = 0.5f * v * (1.f + erff(v * 0.7071067811865476f));
            splt(v, g_x_hi[(size_t)row * FEAT + col], g_x_lo[(size_t)row * FEAT + col]);
        }
    }
}

// ---------------- gates GEMM + in-register LSTM cell --------------------------------
template <bool FIRST>
__global__ void __launch_bounds__(256, 1) gates_mma(int t, const float* __restrict__ bih,
                                                    const float* __restrict__ bhh) {
    extern __shared__ char sm[];
    const uint32_t smu = s2u(sm);
    const int tid = threadIdx.x, lane = tid & 31, wid = tid >> 5;
    const int wm = wid >> 2, wn = wid & 3;
    const int m0 = blockIdx.x * 128, ny = blockIdx.y;

    const bf16* hp_hi = (t & 1) ? g_hA_hi : g_hB_hi;
    const bf16* hp_lo = (t & 1) ? g_hA_lo : g_hB_lo;
    bf16* ho_hi = (t & 1) ? g_hB_hi : g_hA_hi;
    bf16* ho_lo = (t & 1) ? g_hB_lo : g_hA_lo;

    float* bs = reinterpret_cast<float*>(sm + OFF_BIAS);
    {
        int wn2 = tid >> 6, hcg = (tid >> 5) & 1, gate = (tid >> 3) & 3, h8 = tid & 7;
        int hidden = ny * 64 + wn2 * 16 + hcg * 8 + h8;
        bs[tid] = bih[gate * HID + hidden] + bhh[gate * HID + hidden];
    }

    const int NC = FIRST ? 8 : 40;
    float acc[4][8][4];
#pragma unroll
    for (int i = 0; i < 4; ++i)
#pragma unroll
        for (int j = 0; j < 8; ++j)
#pragma unroll
            for (int e = 0; e < 4; ++e) acc[i][j][e] = 0.f;

    auto issue_load = [&](int cs) {
        const int kc = cs * 32;
        const bf16 *aH, *aL; int aK;
        if (FIRST || kc < 256) {
            aH = g_x_hi + (size_t)m0 * FEAT + kc;
            aL = g_x_lo + (size_t)m0 * FEAT + kc; aK = FEAT;
        } else {
            aH = hp_hi + (size_t)m0 * HID + (kc - 256);
            aL = hp_lo + (size_t)m0 * HID + (kc - 256); aK = HID;
        }
        const size_t bo = (size_t)(ny * 256) * 1280 + kc;
        load_chunk(smu + (cs % 3) * STG, aH, aL, aK, g_Wg_hi + bo, g_Wg_lo + bo, 1280, tid);
        CPCOMMIT();
    };

    issue_load(0); issue_load(1); issue_load(2);
    for (int cs = 0; cs < NC; ++cs) {
        CPWAIT2();
        __syncthreads();
        compute_chunk(smu + (cs % 3) * STG, acc, wm, wn, lane);
        __syncthreads();
        if (cs + 3 < NC) issue_load(cs + 3); else CPCOMMIT();
    }

    // in-register LSTM cell epilogue: acc col j = hcg*4 + gate
    const int lane4 = lane >> 2, lq = lane & 3;
#pragma unroll
    for (int i = 0; i < 4; ++i)
#pragma unroll
        for (int rp = 0; rp < 2; ++rp) {
            const int row = m0 + wm * 64 + i * 16 + lane4 + rp * 8;
#pragma unroll
            for (int hcg = 0; hcg < 2; ++hcg) {
                const int h8b = lq * 2;
                const int hidden = ny * 64 + wn * 16 + hcg * 8 + h8b;
                const size_t base = (size_t)row * HID + hidden;
                const int bb = wn * 64 + hcg * 32 + h8b;
                float2 cold = make_float2(0.f, 0.f);
                if (!FIRST) cold = *reinterpret_cast<const float2*>(&g_c[base]);
                float cn[2];
                union { bf16 b[2]; uint32_t u; } Hh, Hl;
#pragma unroll
                for (int eb = 0; eb < 2; ++eb) {
                    const int e = rp * 2 + eb;
                    const float gi = acc[i][hcg * 4 + 0][e] + bs[bb + 0 + eb];
                    const float gf = acc[i][hcg * 4 + 1][e] + bs[bb + 8 + eb];
                    const float gg = acc[i][hcg * 4 + 2][e] + bs[bb + 16 + eb];
                    const float go = acc[i][hcg * 4 + 3][e] + bs[bb + 24 + eb];
                    const float cp = FIRST ? 0.f : (eb ? cold.y : cold.x);
                    const float c2 = sig_(gf) * cp + sig_(gi) * tanh_(gg);
                    cn[eb] = c2;
                    splt(sig_(go) * tanh_(c2), Hh.b[eb], Hl.b[eb]);
                }
                *reinterpret_cast<float2*>(&g_c[base]) = make_float2(cn[0], cn[1]);
                *reinterpret_cast<uint32_t*>(&ho_hi[base]) = Hh.u;
                *reinterpret_cast<uint32_t*>(&ho_lo[base]) = Hl.u;
            }
        }
}

// ---------------- heads GEMM: mu | softplus sigma | z --------------------------------
__global__ void __launch_bounds__(256, 1) heads_mma(int t, const float* __restrict__ bmu,
                                                    const float* __restrict__ bsp,
                                                    const float* __restrict__ eps,
                                                    float* __restrict__ zs,
                                                    float* __restrict__ mus,
                                                    float* __restrict__ sgs) {
    extern __shared__ char sm[];
    const uint32_t smu = s2u(sm);
    const int tid = threadIdx.x, lane = tid & 31, wid = tid >> 5;
    const int wm = wid >> 2, wn = wid & 3;
    const int m0 = blockIdx.x * 128, nb = blockIdx.y;

    const bf16* hc_hi = (t & 1) ? g_hB_hi : g_hA_hi;
    const bf16* hc_lo = (t & 1) ? g_hB_lo : g_hA_lo;

    float* bs = reinterpret_cast<float*>(sm + OFF_BIAS);
    {
        int wn2 = tid >> 6, hcg = (tid >> 4) & 3, head = (tid >> 3) & 1, h8 = tid & 7;
        int f = nb * 128 + wn2 * 32 + hcg * 8 + h8;
        bs[tid] = head ? bsp[f] : bmu[f];
    }

    const int NC = 32;
    float acc[4][8][4];
#pragma unroll
    for (int i = 0; i < 4; ++i)
#pragma unroll
        for (int j = 0; j < 8; ++j)
#pragma unroll
            for (int e = 0; e < 4; ++e) acc[i][j][e] = 0.f;

    auto issue_load = [&](int cs) {
        const int kc = cs * 32;
        const bf16* aH = hc_hi + (size_t)m0 * HID + kc;
        const bf16* aL = hc_lo + (size_t)m0 * HID + kc;
        const size_t bo = (size_t)(nb * 256) * 1024 + kc;
        load_chunk(smu + (cs % 3) * STG, aH, aL, HID, g_Wo_hi + bo, g_Wo_lo + bo, 1024, tid);
        CPCOMMIT();
    };

    issue_load(0); issue_load(1); issue_load(2);
    for (int cs = 0; cs < NC; ++cs) {
        CPWAIT2();
        __syncthreads();
        compute_chunk(smu + (cs % 3) * STG, acc, wm, wn, lane);
        __syncthreads();
        if (cs + 3 < NC) issue_load(cs + 3); else CPCOMMIT();
    }

    // in-register heads epilogue: acc col j = hcg*2 + head
    const int lane4 = lane >> 2, lq = lane & 3;
#pragma unroll
    for (int i = 0; i < 4; ++i)
#pragma unroll
        for (int rp = 0; rp < 2; ++rp) {
            const int row = m0 + wm * 64 + i * 16 + lane4 + rp * 8;
#pragma unroll
            for (int hcg = 0; hcg < 4; ++hcg) {
                const int h8b = lq * 2;
                const int f = nb * 128 + wn * 32 + hcg * 8 + h8b;
                const size_t o = (size_t)t * B_SZ * FEAT + (size_t)row * FEAT + f;
                const size_t xb = (size_t)row * FEAT + f;
                const int bb = wn * 64 + hcg * 16 + h8b;
                const float2 ev = *reinterpret_cast<const float2*>(&eps[o]);
                float zv[2], mv[2], sv[2];
                union { bf16 b[2]; uint32_t u; } Zh, Zl;
#pragma unroll
                for (int eb = 0; eb < 2; ++eb) {
                    const int e = rp * 2 + eb;
                    const float mu = acc[i][hcg * 2 + 0][e] + bs[bb + 0 + eb];
                    const float sg = sp_(acc[i][hcg * 2 + 1][e] + bs[bb + 8 + eb]);
                    const float z = mu + sg * (eb ? ev.y : ev.x);
                    mv[eb] = mu; sv[eb] = sg; zv[eb] = z;
                    splt(z, Zh.b[eb], Zl.b[eb]);
                }
                *reinterpret_cast<float2*>(&zs[o])  = make_float2(zv[0], zv[1]);
                *reinterpret_cast<float2*>(&mus[o]) = make_float2(mv[0], mv[1]);
                *reinterpret_cast<float2*>(&sgs[o]) = make_float2(sv[0], sv[1]);
                *reinterpret_cast<uint32_t*>(&g_x_hi[xb]) = Zh.u;
                *reinterpret_cast<uint32_t*>(&g_x_lo[xb]) = Zl.u;
            }
        }
}

// ---------------- launch --------------------------------------------------------------
extern "C" void kernel_launch(void* const* d_in, const int* in_sizes, int n_in,
                              void* d_out, int out_size) {
    (void)in_sizes; (void)n_in; (void)out_size;
    const float* S   = (const float*)d_in[0];
    const float* eps = (const float*)d_in[1];
    const float* We  = (const float*)d_in[3];
    const float* be  = (const float*)d_in[4];
    const float* Wih = (const float*)d_in[5];
    const float* Whh = (const float*)d_in[6];
    const float* bih = (const float*)d_in[7];
    const float* bhh = (const float*)d_in[8];
    const float* Wmu = (const float*)d_in[9];
    const float* bmu = (const float*)d_in[10];
    const float* Wsp = (const float*)d_in[11];
    const float* bsp = (const float*)d_in[12];

    float* out = (float*)d_out;
    const size_t slab = (size_t)NSLOTS * B_SZ * FEAT;
    float *zs = out, *mus = out + slab, *sgs = out + 2 * slab;

    static bool attr_done = false;
    if (!attr_done) {
        cudaFuncSetAttribute(gates_mma<true>,  cudaFuncAttributeMaxDynamicSharedMemorySize, SMEM_T);
        cudaFuncSetAttribute(gates_mma<false>, cudaFuncAttributeMaxDynamicSharedMemorySize, SMEM_T);
        cudaFuncSetAttribute(heads_mma,        cudaFuncAttributeMaxDynamicSharedMemorySize, SMEM_T);
        attr_done = true;
    }

    conv_weights<<<22528, 256>>>(Wih, Whh, Wmu, Wsp);
    enc_kernel<<<dim3(B_SZ / 64, FEAT / 32), 256>>>(S, We, be);

    for (int t = 0; t < NSLOTS; ++t) {
        if (t == 0)
            gates_mma<true><<<dim3(B_SZ / 128, 16), 256, SMEM_T>>>(t, bih, bhh);
        else
            gates_mma<false><<<dim3(B_SZ / 128, 16), 256, SMEM_T>>>(t, bih, bhh);
        heads_mma<<<dim3(B_SZ / 128, 2), 256, SMEM_T>>>(t, bmu, bsp, eps, zs, mus, sgs);
    }
}

// round 13
// speedup vs baseline: 1.7317x; 1.0006x over previous
#include <cuda_runtime.h>
#include <cuda_bf16.h>
#include <cstdint>
#include <math.h>

#define B_SZ 16384
#define SCENE 256
#define FEAT 256
#define HID 1024
#define NSLOTS 8
typedef __nv_bfloat16 bf16;

// ---------------- device scratch ---------------------------------------------
// gates weights packed: row = ny*256 + wn*64 + hcg*32 + gate*8 + h8 ; K = 1280
// (hidden unit = ny*64 + wn*16 + hcg*8 + h8, ny in [0,16), wn in [0,4))
__device__ bf16 g_Wg_hi[4096 * 1280];
__device__ bf16 g_Wg_lo[4096 * 1280];
// heads weights packed: row = nb*256 + wn*64 + hcg*16 + head*8 + h8 ; K = 1024
// (feature = nb*128 + wn*32 + hcg*8 + h8, nb in [0,2))
__device__ bf16 g_Wo_hi[512 * 1024];
__device__ bf16 g_Wo_lo[512 * 1024];
__device__ bf16 g_x_hi[B_SZ * FEAT];
__device__ bf16 g_x_lo[B_SZ * FEAT];
__device__ bf16 g_hA_hi[B_SZ * HID];
__device__ bf16 g_hA_lo[B_SZ * HID];
__device__ bf16 g_hB_hi[B_SZ * HID];
__device__ bf16 g_hB_lo[B_SZ * HID];
__device__ float g_c[B_SZ * HID];

// ---------------- helpers -----------------------------------------------------
__device__ __forceinline__ uint32_t s2u(const void* p) {
    uint32_t a;
    asm("{.reg .u64 t; cvta.to.shared.u64 t,%1; cvt.u32.u64 %0,t;}" : "=r"(a) : "l"(p));
    return a;
}
#define CP16(dst, src) asm volatile("cp.async.cg.shared.global [%0], [%1], 16;" ::"r"(dst), "l"(src))
#define CPCOMMIT() asm volatile("cp.async.commit_group;" ::: "memory")
#define CPWAIT2() asm volatile("cp.async.wait_group 2;" ::: "memory")

__device__ __forceinline__ void ldsm4(uint32_t* r, uint32_t a) {
    asm volatile("ldmatrix.sync.aligned.m8n8.x4.shared.b16 {%0,%1,%2,%3},[%4];"
                 : "=r"(r[0]), "=r"(r[1]), "=r"(r[2]), "=r"(r[3]) : "r"(a));
}
__device__ __forceinline__ void mma16816(float* c, const uint32_t* a, const uint32_t* b) {
    asm volatile("mma.sync.aligned.m16n8k16.row.col.f32.bf16.bf16.f32 "
                 "{%0,%1,%2,%3},{%4,%5,%6,%7},{%8,%9},{%0,%1,%2,%3};"
                 : "+f"(c[0]), "+f"(c[1]), "+f"(c[2]), "+f"(c[3])
                 : "r"(a[0]), "r"(a[1]), "r"(a[2]), "r"(a[3]), "r"(b[0]), "r"(b[1]));
}

__device__ __forceinline__ float sig_(float x) { return 1.f / (1.f + __expf(-x)); }
__device__ __forceinline__ float tanh_(float x) { return 2.f * sig_(2.f * x) - 1.f; }
__device__ __forceinline__ float sp_(float x) { return fmaxf(x, 0.f) + __logf(1.f + __expf(-fabsf(x))); }
__device__ __forceinline__ void splt(float v, bf16& h, bf16& l) {
    h = __float2bfloat16(v); l = __float2bfloat16(v - __bfloat162float(h));
}

// ---------------- smem layout ---------------------------------------------------
// per stage (k32 chunk, 128x256 tile): A_hi | A_lo (128 rows x 80B), B_hi | B_lo (256 rows x 80B)
#define A_SUB 10240
#define OFF_ALO A_SUB
#define OFF_BHI (2 * A_SUB)                  // 20480
#define OFF_BLO (2 * A_SUB + 20480)          // 40960
#define STG 61440
#define OFF_BIAS (3 * STG)                   // 184320
#define SMEM_T (OFF_BIAS + 1024)             // 185344 -> 1 CTA/SM, 8 warps, 255-reg cap

// ---------------- fused chunk loader (hi+lo, A+B), 256 threads -------------------
__device__ __forceinline__ void load_chunk(uint32_t stg,
                                           const bf16* __restrict__ aHi, const bf16* __restrict__ aLo, int aK,
                                           const bf16* __restrict__ bHi, const bf16* __restrict__ bLo, int bK,
                                           int tid) {
#pragma unroll
    for (int q = 0; q < 2; ++q) {              // A: 512 lines (128 rows x 4 chunks)
        const int idx = tid + q * 256;
        const int r = idx >> 2, ch = idx & 3;
        CP16(stg + r * 80 + ch * 16,           (const char*)(aHi + (size_t)r * aK) + ch * 16);
        CP16(stg + OFF_ALO + r * 80 + ch * 16, (const char*)(aLo + (size_t)r * aK) + ch * 16);
    }
#pragma unroll
    for (int q = 0; q < 4; ++q) {              // B: 1024 lines (256 rows x 4 chunks)
        const int idx = tid + q * 256;
        const int r = idx >> 2, ch = idx & 3;
        CP16(stg + OFF_BHI + r * 80 + ch * 16, (const char*)(bHi + (size_t)r * bK) + ch * 16);
        CP16(stg + OFF_BLO + r * 80 + ch * 16, (const char*)(bLo + (size_t)r * bK) + ch * 16);
    }
}

// ---------------- compute one fused k32 chunk (3 split terms) --------------------
// 8 warps: wm in [0,2) (M64), wn in [0,4) (N64); warp tile 64x64
__device__ __forceinline__ void compute_chunk(uint32_t sa, float acc[4][8][4],
                                              int wm, int wn, int lane) {
#pragma unroll
    for (int kk = 0; kk < 2; ++kk) {
        uint32_t ahi[4][4], alo[4][4];
#pragma unroll
        for (int i = 0; i < 4; ++i) {
            const int row = wm * 64 + i * 16 + (lane & 15);
            const uint32_t off = row * 80 + kk * 32 + ((lane >> 4) << 4);
            ldsm4(ahi[i], sa + off);
            ldsm4(alo[i], sa + OFF_ALO + off);
        }
#pragma unroll
        for (int jp = 0; jp < 4; ++jp) {
            const int brow = wn * 64 + jp * 16 + ((lane & 7) | ((lane >> 4) << 3));
            const uint32_t boff = brow * 80 + kk * 32 + (((lane >> 3) & 1) << 4);
            uint32_t bh[4], bl[4];
            ldsm4(bh, sa + OFF_BHI + boff);
#pragma unroll
            for (int i = 0; i < 4; ++i) {
                mma16816(acc[i][jp * 2 + 0], ahi[i], &bh[0]);
                mma16816(acc[i][jp * 2 + 1], ahi[i], &bh[2]);
            }
            ldsm4(bl, sa + OFF_BLO + boff);
#pragma unroll
            for (int i = 0; i < 4; ++i) {
                mma16816(acc[i][jp * 2 + 0], alo[i], &bh[0]);
                mma16816(acc[i][jp * 2 + 1], alo[i], &bh[2]);
            }
#pragma unroll
            for (int i = 0; i < 4; ++i) {
                mma16816(acc[i][jp * 2 + 0], ahi[i], &bl[0]);
                mma16816(acc[i][jp * 2 + 1], ahi[i], &bl[2]);
            }
        }
    }
}

// ---------------- weight repack ---------------------------------------------------
__global__ void conv_weights(const float* __restrict__ Wih, const float* __restrict__ Whh,
                             const float* __restrict__ Wmu, const float* __restrict__ Wsp) {
    int i = blockIdx.x * 256 + threadIdx.x;
    const int NG = 4096 * 1280;
    if (i < NG) {
        int r = i / 1280, k = i - r * 1280;
        int ny = r >> 8, w = r & 255;
        int wn = w >> 6, hcg = (w >> 5) & 1, gate = (w >> 3) & 3, h8 = w & 7;
        int hidden = ny * 64 + wn * 16 + hcg * 8 + h8;
        int o = gate * HID + hidden;
        float v = (k < FEAT) ? Wih[(size_t)o * FEAT + k] : Whh[(size_t)o * HID + (k - FEAT)];
        splt(v, g_Wg_hi[i], g_Wg_lo[i]);
    } else {
        int j = i - NG;
        if (j < 512 * 1024) {
            int r = j / 1024, k = j - r * 1024;
            int nb = r >> 8, w = r & 255;
            int wn = w >> 6, hcg = (w >> 4) & 3, head = (w >> 3) & 1, h8 = w & 7;
            int f = nb * 128 + wn * 32 + hcg * 8 + h8;
            float v = head ? Wsp[(size_t)f * HID + k] : Wmu[(size_t)f * HID + k];
            splt(v, g_Wo_hi[j], g_Wo_lo[j]);
        }
    }
}

// ---------------- encoder (SIMT fp32) ----------------------------------------------
__global__ void __launch_bounds__(256, 2) enc_kernel(const float* __restrict__ S,
                                                     const float* __restrict__ We,
                                                     const float* __restrict__ be) {
    __shared__ float As[16 * 65], Ws[16 * 33];
    const int tid = threadIdx.x, tx = tid & 15, ty = tid >> 4;
    const int m0 = blockIdx.x * 64, n0 = blockIdx.y * 32;
    float acc[8];
#pragma unroll
    for (int i = 0; i < 8; ++i) acc[i] = 0.f;
    const int rl = tid >> 2, kl = (tid & 3) * 4;
    for (int k0 = 0; k0 < SCENE; k0 += 16) {
        float4 v = *reinterpret_cast<const float4*>(&S[(size_t)(m0 + rl) * SCENE + k0 + kl]);
        As[(kl + 0) * 65 + rl] = v.x; As[(kl + 1) * 65 + rl] = v.y;
        As[(kl + 2) * 65 + rl] = v.z; As[(kl + 3) * 65 + rl] = v.w;
        if (tid < 128) {
            int c = tid >> 2, kc = (tid & 3) * 4;
            float4 w = *reinterpret_cast<const float4*>(&We[(size_t)(n0 + c) * SCENE + k0 + kc]);
            Ws[(kc + 0) * 33 + c] = w.x; Ws[(kc + 1) * 33 + c] = w.y;
            Ws[(kc + 2) * 33 + c] = w.z; Ws[(kc + 3) * 33 + c] = w.w;
        }
        __syncthreads();
#pragma unroll
        for (int k = 0; k < 16; ++k) {
            float a0 = As[k * 65 + ty * 4], a1 = As[k * 65 + ty * 4 + 1];
            float a2 = As[k * 65 + ty * 4 + 2], a3 = As[k * 65 + ty * 4 + 3];
            float w0 = Ws[k * 33 + tx * 2], w1 = Ws[k * 33 + tx * 2 + 1];
            acc[0] = fmaf(a0, w0, acc[0]); acc[1] = fmaf(a0, w1, acc[1]);
            acc[2] = fmaf(a1, w0, acc[2]); acc[3] = fmaf(a1, w1, acc[3]);
            acc[4] = fmaf(a2, w0, acc[4]); acc[5] = fmaf(a2, w1, acc[5]);
            acc[6] = fmaf(a3, w0, acc[6]); acc[7] = fmaf(a3, w1, acc[7]);
        }
        __syncthreads();
    }
#pragma unroll
    for (int c = 0; c < 2; ++c) {
        const int col = n0 + tx * 2 + c;
        const float b = be[col];
#pragma unroll
        for (int r = 0; r < 4; ++r) {
            const int row = m0 + ty * 4 + r;
            float v = acc[r * 2 + c] + b;
            v = 0.5f * v * (1.f + erff(v * 0.7071067811865476f));
            splt(v, g_x_hi[(size_t)row * FEAT + col], g_x_lo[(size_t)row * FEAT + col]);
        }
    }
}

// ---------------- gates GEMM + in-register LSTM cell --------------------------------
template <bool FIRST>
__global__ void __launch_bounds__(256, 1) gates_mma(int t, const float* __restrict__ bih,
                                                    const float* __restrict__ bhh) {
    extern __shared__ char sm[];
    const uint32_t smu = s2u(sm);
    const int tid = threadIdx.x, lane = tid & 31, wid = tid >> 5;
    const int wm = wid >> 2, wn = wid & 3;
    const int m0 = blockIdx.x * 128, ny = blockIdx.y;

    const bf16* hp_hi = (t & 1) ? g_hA_hi : g_hB_hi;
    const bf16* hp_lo = (t & 1) ? g_hA_lo : g_hB_lo;
    bf16* ho_hi = (t & 1) ? g_hB_hi : g_hA_hi;
    bf16* ho_lo = (t & 1) ? g_hB_lo : g_hA_lo;

    float* bs = reinterpret_cast<float*>(sm + OFF_BIAS);
    {
        int wn2 = tid >> 6, hcg = (tid >> 5) & 1, gate = (tid >> 3) & 3, h8 = tid & 7;
        int hidden = ny * 64 + wn2 * 16 + hcg * 8 + h8;
        bs[tid] = bih[gate * HID + hidden] + bhh[gate * HID + hidden];
    }

    const int NC = FIRST ? 8 : 40;
    float acc[4][8][4];
#pragma unroll
    for (int i = 0; i < 4; ++i)
#pragma unroll
        for (int j = 0; j < 8; ++j)
#pragma unroll
            for (int e = 0; e < 4; ++e) acc[i][j][e] = 0.f;

    auto issue_load = [&](int cs) {
        const int kc = cs * 32;
        const bf16 *aH, *aL; int aK;
        if (FIRST || kc < 256) {
            aH = g_x_hi + (size_t)m0 * FEAT + kc;
            aL = g_x_lo + (size_t)m0 * FEAT + kc; aK = FEAT;
        } else {
            aH = hp_hi + (size_t)m0 * HID + (kc - 256);
            aL = hp_lo + (size_t)m0 * HID + (kc - 256); aK = HID;
        }
        const size_t bo = (size_t)(ny * 256) * 1280 + kc;
        load_chunk(smu + (cs % 3) * STG, aH, aL, aK, g_Wg_hi + bo, g_Wg_lo + bo, 1280, tid);
        CPCOMMIT();
    };

    issue_load(0); issue_load(1); issue_load(2);
    for (int cs = 0; cs < NC; ++cs) {
        CPWAIT2();
        __syncthreads();
        compute_chunk(smu + (cs % 3) * STG, acc, wm, wn, lane);
        __syncthreads();
        if (cs + 3 < NC) issue_load(cs + 3); else CPCOMMIT();
    }

    // in-register LSTM cell epilogue: acc col j = hcg*4 + gate
    const int lane4 = lane >> 2, lq = lane & 3;
#pragma unroll
    for (int i = 0; i < 4; ++i)
#pragma unroll
        for (int rp = 0; rp < 2; ++rp) {
            const int row = m0 + wm * 64 + i * 16 + lane4 + rp * 8;
#pragma unroll
            for (int hcg = 0; hcg < 2; ++hcg) {
                const int h8b = lq * 2;
                const int hidden = ny * 64 + wn * 16 + hcg * 8 + h8b;
                const size_t base = (size_t)row * HID + hidden;
                const int bb = wn * 64 + hcg * 32 + h8b;
                float2 cold = make_float2(0.f, 0.f);
                if (!FIRST) cold = *reinterpret_cast<const float2*>(&g_c[base]);
                float cn[2];
                union { bf16 b[2]; uint32_t u; } Hh, Hl;
#pragma unroll
                for (int eb = 0; eb < 2; ++eb) {
                    const int e = rp * 2 + eb;
                    const float gi = acc[i][hcg * 4 + 0][e] + bs[bb + 0 + eb];
                    const float gf = acc[i][hcg * 4 + 1][e] + bs[bb + 8 + eb];
                    const float gg = acc[i][hcg * 4 + 2][e] + bs[bb + 16 + eb];
                    const float go = acc[i][hcg * 4 + 3][e] + bs[bb + 24 + eb];
                    const float cp = FIRST ? 0.f : (eb ? cold.y : cold.x);
                    const float c2 = sig_(gf) * cp + sig_(gi) * tanh_(gg);
                    cn[eb] = c2;
                    splt(sig_(go) * tanh_(c2), Hh.b[eb], Hl.b[eb]);
                }
                *reinterpret_cast<float2*>(&g_c[base]) = make_float2(cn[0], cn[1]);
                *reinterpret_cast<uint32_t*>(&ho_hi[base]) = Hh.u;
                *reinterpret_cast<uint32_t*>(&ho_lo[base]) = Hl.u;
            }
        }
}

// ---------------- heads GEMM: mu | softplus sigma | z --------------------------------
__global__ void __launch_bounds__(256, 1) heads_mma(int t, const float* __restrict__ bmu,
                                                    const float* __restrict__ bsp,
                                                    const float* __restrict__ eps,
                                                    float* __restrict__ zs,
                                                    float* __restrict__ mus,
                                                    float* __restrict__ sgs) {
    extern __shared__ char sm[];
    const uint32_t smu = s2u(sm);
    const int tid = threadIdx.x, lane = tid & 31, wid = tid >> 5;
    const int wm = wid >> 2, wn = wid & 3;
    const int m0 = blockIdx.x * 128, nb = blockIdx.y;

    const bf16* hc_hi = (t & 1) ? g_hB_hi : g_hA_hi;
    const bf16* hc_lo = (t & 1) ? g_hB_lo : g_hA_lo;

    float* bs = reinterpret_cast<float*>(sm + OFF_BIAS);
    {
        int wn2 = tid >> 6, hcg = (tid >> 4) & 3, head = (tid >> 3) & 1, h8 = tid & 7;
        int f = nb * 128 + wn2 * 32 + hcg * 8 + h8;
        bs[tid] = head ? bsp[f] : bmu[f];
    }

    const int NC = 32;
    float acc[4][8][4];
#pragma unroll
    for (int i = 0; i < 4; ++i)
#pragma unroll
        for (int j = 0; j < 8; ++j)
#pragma unroll
            for (int e = 0; e < 4; ++e) acc[i][j][e] = 0.f;

    auto issue_load = [&](int cs) {
        const int kc = cs * 32;
        const bf16* aH = hc_hi + (size_t)m0 * HID + kc;
        const bf16* aL = hc_lo + (size_t)m0 * HID + kc;
        const size_t bo = (size_t)(nb * 256) * 1024 + kc;
        load_chunk(smu + (cs % 3) * STG, aH, aL, HID, g_Wo_hi + bo, g_Wo_lo + bo, 1024, tid);
        CPCOMMIT();
    };

    issue_load(0); issue_load(1); issue_load(2);
    for (int cs = 0; cs < NC; ++cs) {
        CPWAIT2();
        __syncthreads();
        compute_chunk(smu + (cs % 3) * STG, acc, wm, wn, lane);
        __syncthreads();
        if (cs + 3 < NC) issue_load(cs + 3); else CPCOMMIT();
    }

    // in-register heads epilogue: acc col j = hcg*2 + head
    const int lane4 = lane >> 2, lq = lane & 3;
#pragma unroll
    for (int i = 0; i < 4; ++i)
#pragma unroll
        for (int rp = 0; rp < 2; ++rp) {
            const int row = m0 + wm * 64 + i * 16 + lane4 + rp * 8;
#pragma unroll
            for (int hcg = 0; hcg < 4; ++hcg) {
                const int h8b = lq * 2;
                const int f = nb * 128 + wn * 32 + hcg * 8 + h8b;
                const size_t o = (size_t)t * B_SZ * FEAT + (size_t)row * FEAT + f;
                const size_t xb = (size_t)row * FEAT + f;
                const int bb = wn * 64 + hcg * 16 + h8b;
                const float2 ev = *reinterpret_cast<const float2*>(&eps[o]);
                float zv[2], mv[2], sv[2];
                union { bf16 b[2]; uint32_t u; } Zh, Zl;
#pragma unroll
                for (int eb = 0; eb < 2; ++eb) {
                    const int e = rp * 2 + eb;
                    const float mu = acc[i][hcg * 2 + 0][e] + bs[bb + 0 + eb];
                    const float sg = sp_(acc[i][hcg * 2 + 1][e] + bs[bb + 8 + eb]);
                    const float z = mu + sg * (eb ? ev.y : ev.x);
                    mv[eb] = mu; sv[eb] = sg; zv[eb] = z;
                    splt(z, Zh.b[eb], Zl.b[eb]);
                }
                *reinterpret_cast<float2*>(&zs[o])  = make_float2(zv[0], zv[1]);
                *reinterpret_cast<float2*>(&mus[o]) = make_float2(mv[0], mv[1]);
                *reinterpret_cast<float2*>(&sgs[o]) = make_float2(sv[0], sv[1]);
                *reinterpret_cast<uint32_t*>(&g_x_hi[xb]) = Zh.u;
                *reinterpret_cast<uint32_t*>(&g_x_lo[xb]) = Zl.u;
            }
        }
}

// ---------------- launch --------------------------------------------------------------
extern "C" void kernel_launch(void* const* d_in, const int* in_sizes, int n_in,
                              void* d_out, int out_size) {
    (void)in_sizes; (void)n_in; (void)out_size;
    const float* S   = (const float*)d_in[0];
    const float* eps = (const float*)d_in[1];
    const float* We  = (const float*)d_in[3];
    const float* be  = (const float*)d_in[4];
    const float* Wih = (const float*)d_in[5];
    const float* Whh = (const float*)d_in[6];
    const float* bih = (const float*)d_in[7];
    const float* bhh = (const float*)d_in[8];
    const float* Wmu = (const float*)d_in[9];
    const float* bmu = (const float*)d_in[10];
    const float* Wsp = (const float*)d_in[11];
    const float* bsp = (const float*)d_in[12];

    float* out = (float*)d_out;
    const size_t slab = (size_t)NSLOTS * B_SZ * FEAT;
    float *zs = out, *mus = out + slab, *sgs = out + 2 * slab;

    static bool attr_done = false;
    if (!attr_done) {
        cudaFuncSetAttribute(gates_mma<true>,  cudaFuncAttributeMaxDynamicSharedMemorySize, SMEM_T);
        cudaFuncSetAttribute(gates_mma<false>, cudaFuncAttributeMaxDynamicSharedMemorySize, SMEM_T);
        cudaFuncSetAttribute(heads_mma,        cudaFuncAttributeMaxDynamicSharedMemorySize, SMEM_T);
        attr_done = true;
    }

    conv_weights<<<22528, 256>>>(Wih, Whh, Wmu, Wsp);
    enc_kernel<<<dim3(B_SZ / 64, FEAT / 32), 256>>>(S, We, be);

    for (int t = 0; t < NSLOTS; ++t) {
        if (t == 0)
            gates_mma<true><<<dim3(B_SZ / 128, 16), 256, SMEM_T>>>(t, bih, bhh);
        else
            gates_mma<false><<<dim3(B_SZ / 128, 16), 256, SMEM_T>>>(t, bih, bhh);
        heads_mma<<<dim3(B_SZ / 128, 2), 256, SMEM_T>>>(t, bmu, bsp, eps, zs, mus, sgs);
    }
}

// round 16
// speedup vs baseline: 2.3569x; 1.3610x over previous
#include <cuda_runtime.h>
#include <cuda_bf16.h>
#include <cstdint>
#include <math.h>

#define B_SZ 16384
#define SCENE 256
#define FEAT 256
#define HID 1024
#define NSLOTS 8
typedef __nv_bfloat16 bf16;

// ---------------- device scratch ---------------------------------------------
// gates weights packed (R7): row = ny*128 + wn*64 + hcg*32 + gate*8 + h8 ; K=1280
// hidden = ny*32 + wn*16 + hcg*8 + h8 ; ny in [0,32), wn in [0,2)
__device__ bf16 g_Wg_hi[4096 * 1280];
__device__ bf16 g_Wg_lo[4096 * 1280];
// heads weights packed (R7): row = nb*128 + wn*64 + hcg*16 + head*8 + h8 ; K=1024
// feature = nb*64 + wn*32 + hcg*8 + h8 ; nb in [0,4), wn in [0,2)
__device__ bf16 g_Wo_hi[512 * 1024];
__device__ bf16 g_Wo_lo[512 * 1024];
__device__ bf16 g_x_hi[B_SZ * FEAT];
__device__ bf16 g_x_lo[B_SZ * FEAT];
__device__ bf16 g_hA_hi[B_SZ * HID];
__device__ bf16 g_hA_lo[B_SZ * HID];
__device__ bf16 g_hB_hi[B_SZ * HID];
__device__ bf16 g_hB_lo[B_SZ * HID];
__device__ float g_c[B_SZ * HID];

// ---------------- helpers -----------------------------------------------------
__device__ __forceinline__ uint32_t s2u(const void* p) {
    uint32_t a;
    asm("{.reg .u64 t; cvta.to.shared.u64 t,%1; cvt.u32.u64 %0,t;}" : "=r"(a) : "l"(p));
    return a;
}
#define CP16(dst, src) asm volatile("cp.async.cg.shared.global [%0], [%1], 16;" ::"r"(dst), "l"(src))
#define CPCOMMIT() asm volatile("cp.async.commit_group;" ::: "memory")
#define CPWAIT1() asm volatile("cp.async.wait_group 1;" ::: "memory")

__device__ __forceinline__ void ldsm4(uint32_t* r, uint32_t a) {
    asm volatile("ldmatrix.sync.aligned.m8n8.x4.shared.b16 {%0,%1,%2,%3},[%4];"
                 : "=r"(r[0]), "=r"(r[1]), "=r"(r[2]), "=r"(r[3]) : "r"(a));
}
__device__ __forceinline__ void mma16816(float* c, const uint32_t* a, const uint32_t* b) {
    asm volatile("mma.sync.aligned.m16n8k16.row.col.f32.bf16.bf16.f32 "
                 "{%0,%1,%2,%3},{%4,%5,%6,%7},{%8,%9},{%0,%1,%2,%3};"
                 : "+f"(c[0]), "+f"(c[1]), "+f"(c[2]), "+f"(c[3])
                 : "r"(a[0]), "r"(a[1]), "r"(a[2]), "r"(a[3]), "r"(b[0]), "r"(b[1]));
}

__device__ __forceinline__ float sig_(float x) { return 1.f / (1.f + __expf(-x)); }
__device__ __forceinline__ float tanh_(float x) { return 2.f * sig_(2.f * x) - 1.f; }
__device__ __forceinline__ float sp_(float x) { return fmaxf(x, 0.f) + __logf(1.f + __expf(-fabsf(x))); }
__device__ __forceinline__ void splt(float v, bf16& h, bf16& l) {
    h = __float2bfloat16(v); l = __float2bfloat16(v - __bfloat162float(h));
}

// ---------------- swizzled smem addressing ------------------------------------
// 64B rows, 4x16B cols, col ^= (row & 3): 2-way max LDSM conflict, no padding.
__device__ __forceinline__ uint32_t swz(int row, int col16) {
    return (uint32_t)(row * 64 + ((col16 ^ (row & 3)) << 4));
}

// gates stage: AH | AL | BH | BL, each 128 rows x 64B
#define G_AL 8192
#define G_BH 16384
#define G_BL 24576
#define G_STG 32768
#define G_BIAS (3 * G_STG)                  // 98304
#define G_SMEM (G_BIAS + 1024)              // 99328 -> 2 CTAs/SM

// heads stage: AH | AL (64 rows), BH | BL (128 rows)
#define H_AL 4096
#define H_BH 8192
#define H_BL 16384
#define H_STG 24576
#define H_BIAS (3 * H_STG)                  // 73728
#define H_SMEM (H_BIAS + 512)               // 74240 -> 3 CTAs/SM

// ---------------- loaders (swizzled) -------------------------------------------
__device__ __forceinline__ void g_load(uint32_t stg,
                                       const bf16* __restrict__ aH, const bf16* __restrict__ aL, int aK,
                                       const bf16* __restrict__ bH, const bf16* __restrict__ bL, int bK,
                                       int tid) {
#pragma unroll
    for (int q = 0; q < 2; ++q) {
        const int idx = tid + q * 256;      // 512 lines: 128 rows x 4 cols
        const int r = idx >> 2, c = idx & 3;
        const uint32_t d = swz(r, c);
        CP16(stg + d,        (const char*)(aH + (size_t)r * aK) + c * 16);
        CP16(stg + G_AL + d, (const char*)(aL + (size_t)r * aK) + c * 16);
        CP16(stg + G_BH + d, (const char*)(bH + (size_t)r * bK) + c * 16);
        CP16(stg + G_BL + d, (const char*)(bL + (size_t)r * bK) + c * 16);
    }
    CPCOMMIT();
}
__device__ __forceinline__ void h_load(uint32_t stg,
                                       const bf16* __restrict__ aH, const bf16* __restrict__ aL,
                                       const bf16* __restrict__ bH, const bf16* __restrict__ bL,
                                       int tid) {
#pragma unroll
    for (int q = 0; q < 2; ++q) {           // A: 256 lines (64 rows x 4 cols)
        const int idx = tid + q * 128;
        const int r = idx >> 2, c = idx & 3;
        const uint32_t d = swz(r, c);
        CP16(stg + d,        (const char*)(aH + (size_t)r * HID) + c * 16);
        CP16(stg + H_AL + d, (const char*)(aL + (size_t)r * HID) + c * 16);
    }
#pragma unroll
    for (int q = 0; q < 4; ++q) {           // B: 512 lines (128 rows x 4 cols)
        const int idx = tid + q * 128;
        const int r = idx >> 2, c = idx & 3;
        const uint32_t d = swz(r, c);
        CP16(stg + H_BH + d, (const char*)(bH + (size_t)r * 1024) + c * 16);
        CP16(stg + H_BL + d, (const char*)(bL + (size_t)r * 1024) + c * 16);
    }
    CPCOMMIT();
}

// ---------------- compute one fused k32 chunk; warp tile 32x64 ------------------
template <int ALO, int BHI, int BLO>
__device__ __forceinline__ void compute_chunk(uint32_t sa, float acc[2][8][4],
                                              int wm, int wn, int lane) {
#pragma unroll
    for (int kk = 0; kk < 2; ++kk) {
        uint32_t ahi[2][4], alo[2][4];
        const int acol = kk * 2 + (lane >> 4);
#pragma unroll
        for (int i = 0; i < 2; ++i) {
            const int row = wm * 32 + i * 16 + (lane & 15);
            ldsm4(ahi[i], sa + swz(row, acol));
            ldsm4(alo[i], sa + ALO + swz(row, acol));
        }
        const int bcol = kk * 2 + ((lane >> 3) & 1);
#pragma unroll
        for (int jp = 0; jp < 4; ++jp) {
            const int brow = wn * 64 + jp * 16 + ((lane & 7) | ((lane >> 4) << 3));
            uint32_t bh[4], bl[4];
            ldsm4(bh, sa + BHI + swz(brow, bcol));
#pragma unroll
            for (int i = 0; i < 2; ++i) {
                mma16816(acc[i][jp * 2 + 0], ahi[i], &bh[0]);
                mma16816(acc[i][jp * 2 + 1], ahi[i], &bh[2]);
            }
            ldsm4(bl, sa + BLO + swz(brow, bcol));
#pragma unroll
            for (int i = 0; i < 2; ++i) {
                mma16816(acc[i][jp * 2 + 0], alo[i], &bh[0]);
                mma16816(acc[i][jp * 2 + 1], alo[i], &bh[2]);
            }
#pragma unroll
            for (int i = 0; i < 2; ++i) {
                mma16816(acc[i][jp * 2 + 0], ahi[i], &bl[0]);
                mma16816(acc[i][jp * 2 + 1], ahi[i], &bl[2]);
            }
        }
    }
}

// ---------------- weight repack (R7 layouts) ------------------------------------
__global__ void conv_weights(const float* __restrict__ Wih, const float* __restrict__ Whh,
                             const float* __restrict__ Wmu, const float* __restrict__ Wsp) {
    int i = blockIdx.x * 256 + threadIdx.x;
    const int NG = 4096 * 1280;
    if (i < NG) {
        int r = i / 1280, k = i - r * 1280;
        int ny = r >> 7, w = r & 127;
        int wn = w >> 6, hcg = (w >> 5) & 1, gate = (w >> 3) & 3, h8 = w & 7;
        int hidden = ny * 32 + wn * 16 + hcg * 8 + h8;
        int o = gate * HID + hidden;
        float v = (k < FEAT) ? Wih[(size_t)o * FEAT + k] : Whh[(size_t)o * HID + (k - FEAT)];
        splt(v, g_Wg_hi[i], g_Wg_lo[i]);
    } else {
        int j = i - NG;
        if (j < 512 * 1024) {
            int r = j / 1024, k = j - r * 1024;
            int nb = r >> 7, w = r & 127;
            int wn = w >> 6, hcg = (w >> 4) & 3, head = (w >> 3) & 1, h8 = w & 7;
            int f = nb * 64 + wn * 32 + hcg * 8 + h8;
            float v = head ? Wsp[(size_t)f * HID + k] : Wmu[(size_t)f * HID + k];
            splt(v, g_Wo_hi[j], g_Wo_lo[j]);
        }
    }
}

// ---------------- encoder (SIMT fp32) ----------------------------------------------
__global__ void __launch_bounds__(256, 2) enc_kernel(const float* __restrict__ S,
                                                     const float* __restrict__ We,
                                                     const float* __restrict__ be) {
    __shared__ float As[16 * 65], Ws[16 * 33];
    const int tid = threadIdx.x, tx = tid & 15, ty = tid >> 4;
    const int m0 = blockIdx.x * 64, n0 = blockIdx.y * 32;
    float acc[8];
#pragma unroll
    for (int i = 0; i < 8; ++i) acc[i] = 0.f;
    const int rl = tid >> 2, kl = (tid & 3) * 4;
    for (int k0 = 0; k0 < SCENE; k0 += 16) {
        float4 v = *reinterpret_cast<const float4*>(&S[(size_t)(m0 + rl) * SCENE + k0 + kl]);
        As[(kl + 0) * 65 + rl] = v.x; As[(kl + 1) * 65 + rl] = v.y;
        As[(kl + 2) * 65 + rl] = v.z; As[(kl + 3) * 65 + rl] = v.w;
        if (tid < 128) {
            int c = tid >> 2, kc = (tid & 3) * 4;
            float4 w = *reinterpret_cast<const float4*>(&We[(size_t)(n0 + c) * SCENE + k0 + kc]);
            Ws[(kc + 0) * 33 + c] = w.x; Ws[(kc + 1) * 33 + c] = w.y;
            Ws[(kc + 2) * 33 + c] = w.z; Ws[(kc + 3) * 33 + c] = w.w;
        }
        __syncthreads();
#pragma unroll
        for (int k = 0; k < 16; ++k) {
            float a0 = As[k * 65 + ty * 4], a1 = As[k * 65 + ty * 4 + 1];
            float a2 = As[k * 65 + ty * 4 + 2], a3 = As[k * 65 + ty * 4 + 3];
            float w0 = Ws[k * 33 + tx * 2], w1 = Ws[k * 33 + tx * 2 + 1];
            acc[0] = fmaf(a0, w0, acc[0]); acc[1] = fmaf(a0, w1, acc[1]);
            acc[2] = fmaf(a1, w0, acc[2]); acc[3] = fmaf(a1, w1, acc[3]);
            acc[4] = fmaf(a2, w0, acc[4]); acc[5] = fmaf(a2, w1, acc[5]);
            acc[6] = fmaf(a3, w0, acc[6]); acc[7] = fmaf(a3, w1, acc[7]);
        }
        __syncthreads();
    }
#pragma unroll
    for (int c = 0; c < 2; ++c) {
        const int col = n0 + tx * 2 + c;
        const float b = be[col];
#pragma unroll
        for (int r = 0; r < 4; ++r) {
            const int row = m0 + ty * 4 + r;
            float v = acc[r * 2 + c] + b;
            v = 0.5f * v * (1.f + erff(v * 0.7071067811865476f));
            splt(v, g_x_hi[(size_t)row * FEAT + col], g_x_lo[(size_t)row * FEAT + col]);
        }
    }
}

// ---------------- gates GEMM + in-register LSTM cell -------------------------------
// CTA 128x128, 256 threads, 8 warps: wm = wid>>1 in [0,4), wn = wid&1 in [0,2)
template <bool FIRST>
__global__ void __launch_bounds__(256, 2) gates_mma(int t, const float* __restrict__ bih,
                                                    const float* __restrict__ bhh) {
    extern __shared__ char sm[];
    const uint32_t smu = s2u(sm);
    const int tid = threadIdx.x, lane = tid & 31, wid = tid >> 5;
    const int wm = wid >> 1, wn = wid & 1;
    const int m0 = blockIdx.x * 128, ny = blockIdx.y;

    const bf16* hp_hi = (t & 1) ? g_hA_hi : g_hB_hi;
    const bf16* hp_lo = (t & 1) ? g_hA_lo : g_hB_lo;
    bf16* ho_hi = (t & 1) ? g_hB_hi : g_hA_hi;
    bf16* ho_lo = (t & 1) ? g_hB_lo : g_hA_lo;

    float* bs = reinterpret_cast<float*>(sm + G_BIAS);
    if (tid < 128) {
        int wn2 = tid >> 6, hcg = (tid >> 5) & 1, gate = (tid >> 3) & 3, h8 = tid & 7;
        int hidden = ny * 32 + wn2 * 16 + hcg * 8 + h8;
        bs[tid] = bih[gate * HID + hidden] + bhh[gate * HID + hidden];
    }

    const int NC = FIRST ? 8 : 40;
    float acc[2][8][4];
#pragma unroll
    for (int i = 0; i < 2; ++i)
#pragma unroll
        for (int j = 0; j < 8; ++j)
#pragma unroll
            for (int e = 0; e < 4; ++e) acc[i][j][e] = 0.f;

    auto issue_load = [&](int cs) {
        const int kc = cs * 32;
        const bf16 *aH, *aL; int aK;
        if (FIRST || kc < 256) {
            aH = g_x_hi + (size_t)m0 * FEAT + kc;
            aL = g_x_lo + (size_t)m0 * FEAT + kc; aK = FEAT;
        } else {
            aH = hp_hi + (size_t)m0 * HID + (kc - 256);
            aL = hp_lo + (size_t)m0 * HID + (kc - 256); aK = HID;
        }
        const size_t bo = (size_t)(ny * 128) * 1280 + kc;
        g_load(smu + (cs % 3) * G_STG, aH, aL, aK, g_Wg_hi + bo, g_Wg_lo + bo, 1280, tid);
    };

    issue_load(0); issue_load(1);
    for (int cs = 0; cs < NC; ++cs) {
        CPWAIT1();
        __syncthreads();                    // publishes stage cs; guards overwrite of cs-1
        compute_chunk<G_AL, G_BH, G_BL>(smu + (cs % 3) * G_STG, acc, wm, wn, lane);
        if (cs + 2 < NC) issue_load(cs + 2); else CPCOMMIT();
    }

    // in-register LSTM cell epilogue: acc col j = hcg*4 + gate
    const int lane4 = lane >> 2, lq = lane & 3;
#pragma unroll
    for (int i = 0; i < 2; ++i)
#pragma unroll
        for (int rp = 0; rp < 2; ++rp) {
            const int row = m0 + wm * 32 + i * 16 + lane4 + rp * 8;
#pragma unroll
            for (int hcg = 0; hcg < 2; ++hcg) {
                const int h8b = lq * 2;
                const int hidden = ny * 32 + wn * 16 + hcg * 8 + h8b;
                const size_t base = (size_t)row * HID + hidden;
                const int bb = wn * 64 + hcg * 32 + h8b;
                float2 cold = make_float2(0.f, 0.f);
                if (!FIRST) cold = *reinterpret_cast<const float2*>(&g_c[base]);
                float cn[2];
                union { bf16 b[2]; uint32_t u; } Hh, Hl;
#pragma unroll
                for (int eb = 0; eb < 2; ++eb) {
                    const int e = rp * 2 + eb;
                    const float gi = acc[i][hcg * 4 + 0][e] + bs[bb + 0 + eb];
                    const float gf = acc[i][hcg * 4 + 1][e] + bs[bb + 8 + eb];
                    const float gg = acc[i][hcg * 4 + 2][e] + bs[bb + 16 + eb];
                    const float go = acc[i][hcg * 4 + 3][e] + bs[bb + 24 + eb];
                    const float cp = FIRST ? 0.f : (eb ? cold.y : cold.x);
                    const float c2 = sig_(gf) * cp + sig_(gi) * tanh_(gg);
                    cn[eb] = c2;
                    splt(sig_(go) * tanh_(c2), Hh.b[eb], Hl.b[eb]);
                }
                *reinterpret_cast<float2*>(&g_c[base]) = make_float2(cn[0], cn[1]);
                *reinterpret_cast<uint32_t*>(&ho_hi[base]) = Hh.u;
                *reinterpret_cast<uint32_t*>(&ho_lo[base]) = Hl.u;
            }
        }
}

// ---------------- heads GEMM: mu | softplus sigma | z -------------------------------
// CTA 64x128, 128 threads, 4 warps: wm = wid>>1 in [0,2), wn = wid&1 in [0,2)
__global__ void __launch_bounds__(128, 3) heads_mma(int t, const float* __restrict__ bmu,
                                                    const float* __restrict__ bsp,
                                                    const float* __restrict__ eps,
                                                    float* __restrict__ zs,
                                                    float* __restrict__ mus,
                                                    float* __restrict__ sgs) {
    extern __shared__ char sm[];
    const uint32_t smu = s2u(sm);
    const int tid = threadIdx.x, lane = tid & 31, wid = tid >> 5;
    const int wm = wid >> 1, wn = wid & 1;
    const int m0 = blockIdx.x * 64, nb = blockIdx.y;

    const bf16* hc_hi = (t & 1) ? g_hB_hi : g_hA_hi;
    const bf16* hc_lo = (t & 1) ? g_hB_lo : g_hA_lo;

    float* bs = reinterpret_cast<float*>(sm + H_BIAS);
    {
        int wn2 = tid >> 6, hcg = (tid >> 4) & 3, head = (tid >> 3) & 1, h8 = tid & 7;
        int f = nb * 64 + wn2 * 32 + hcg * 8 + h8;
        bs[tid] = head ? bsp[f] : bmu[f];
    }

    const int NC = 32;
    float acc[2][8][4];
#pragma unroll
    for (int i = 0; i < 2; ++i)
#pragma unroll
        for (int j = 0; j < 8; ++j)
#pragma unroll
            for (int e = 0; e < 4; ++e) acc[i][j][e] = 0.f;

    auto issue_load = [&](int cs) {
        const int kc = cs * 32;
        const size_t bo = (size_t)(nb * 128) * 1024 + kc;
        h_load(smu + (cs % 3) * H_STG,
               hc_hi + (size_t)m0 * HID + kc, hc_lo + (size_t)m0 * HID + kc,
               g_Wo_hi + bo, g_Wo_lo + bo, tid);
    };

    issue_load(0); issue_load(1);
    for (int cs = 0; cs < NC; ++cs) {
        CPWAIT1();
        __syncthreads();
        compute_chunk<H_AL, H_BH, H_BL>(smu + (cs % 3) * H_STG, acc, wm, wn, lane);
        if (cs + 2 < NC) issue_load(cs + 2); else CPCOMMIT();
    }

    // in-register heads epilogue: acc col j = hcg*2 + head
    const int lane4 = lane >> 2, lq = lane & 3;
#pragma unroll
    for (int i = 0; i < 2; ++i)
#pragma unroll
        for (int rp = 0; rp < 2; ++rp) {
            const int row = m0 + wm * 32 + i * 16 + lane4 + rp * 8;
#pragma unroll
            for (int hcg = 0; hcg < 4; ++hcg) {
                const int h8b = lq * 2;
                const int f = nb * 64 + wn * 32 + hcg * 8 + h8b;
                const size_t o = (size_t)t * B_SZ * FEAT + (size_t)row * FEAT + f;
                const size_t xb = (size_t)row * FEAT + f;
                const int bb = wn * 64 + hcg * 16 + h8b;
                const float2 ev = *reinterpret_cast<const float2*>(&eps[o]);
                float zv[2], mv[2], sv[2];
                union { bf16 b[2]; uint32_t u; } Zh, Zl;
#pragma unroll
                for (int eb = 0; eb < 2; ++eb) {
                    const int e = rp * 2 + eb;
                    const float mu = acc[i][hcg * 2 + 0][e] + bs[bb + 0 + eb];
                    const float sg = sp_(acc[i][hcg * 2 + 1][e] + bs[bb + 8 + eb]);
                    const float z = mu + sg * (eb ? ev.y : ev.x);
                    mv[eb] = mu; sv[eb] = sg; zv[eb] = z;
                    splt(z, Zh.b[eb], Zl.b[eb]);
                }
                *reinterpret_cast<float2*>(&zs[o])  = make_float2(zv[0], zv[1]);
                *reinterpret_cast<float2*>(&mus[o]) = make_float2(mv[0], mv[1]);
                *reinterpret_cast<float2*>(&sgs[o]) = make_float2(sv[0], sv[1]);
                *reinterpret_cast<uint32_t*>(&g_x_hi[xb]) = Zh.u;
                *reinterpret_cast<uint32_t*>(&g_x_lo[xb]) = Zl.u;
            }
        }
}

// ---------------- launch --------------------------------------------------------------
extern "C" void kernel_launch(void* const* d_in, const int* in_sizes, int n_in,
                              void* d_out, int out_size) {
    (void)in_sizes; (void)n_in; (void)out_size;
    const float* S   = (const float*)d_in[0];
    const float* eps = (const float*)d_in[1];
    const float* We  = (const float*)d_in[3];
    const float* be  = (const float*)d_in[4];
    const float* Wih = (const float*)d_in[5];
    const float* Whh = (const float*)d_in[6];
    const float* bih = (const float*)d_in[7];
    const float* bhh = (const float*)d_in[8];
    const float* Wmu = (const float*)d_in[9];
    const float* bmu = (const float*)d_in[10];
    const float* Wsp = (const float*)d_in[11];
    const float* bsp = (const float*)d_in[12];

    float* out = (float*)d_out;
    const size_t slab = (size_t)NSLOTS * B_SZ * FEAT;
    float *zs = out, *mus = out + slab, *sgs = out + 2 * slab;

    static bool attr_done = false;
    if (!attr_done) {
        cudaFuncSetAttribute(gates_mma<true>,  cudaFuncAttributeMaxDynamicSharedMemorySize, G_SMEM);
        cudaFuncSetAttribute(gates_mma<false>, cudaFuncAttributeMaxDynamicSharedMemorySize, G_SMEM);
        cudaFuncSetAttribute(heads_mma,        cudaFuncAttributeMaxDynamicSharedMemorySize, H_SMEM);
        attr_done = true;
    }

    conv_weights<<<22528, 256>>>(Wih, Whh, Wmu, Wsp);
    enc_kernel<<<dim3(B_SZ / 64, FEAT / 32), 256>>>(S, We, be);

    for (int t = 0; t < NSLOTS; ++t) {
        if (t == 0)
            gates_mma<true><<<dim3(B_SZ / 128, 32), 256, G_SMEM>>>(t, bih, bhh);
        else
            gates_mma<false><<<dim3(B_SZ / 128, 32), 256, G_SMEM>>>(t, bih, bhh);
        heads_mma<<<dim3(B_SZ / 64, 4), 128, H_SMEM>>>(t, bmu, bsp, eps, zs, mus, sgs);
    }
}

// round 17
// speedup vs baseline: 2.3718x; 1.0063x over previous
#include <cuda_runtime.h>
#include <cuda_bf16.h>
#include <cstdint>
#include <math.h>

#define B_SZ 16384
#define SCENE 256
#define FEAT 256
#define HID 1024
#define NSLOTS 8
typedef __nv_bfloat16 bf16;

// ---------------- device scratch ---------------------------------------------
// gates weights packed: row r = ny*128 + n; n bits: wn=n>>6, gate=(n>>4)&3,
//   hcg=(n>>3)&1, lq=(n>>1)&3, cb=n&1 -> hidden = ny*32+wn*16+lq*4+cb*2+hcg
__device__ bf16 g_Wg_hi[4096 * 1280];
__device__ bf16 g_Wg_lo[4096 * 1280];
// heads weights packed: row r = nb*128 + n; n bits: wn=n>>6, jp=(n>>4)&3,
//   head=(n>>3)&1, lq=(n>>1)&3, cb=n&1 -> f = nb*64+wn*32+lq*8+cb*4+jp
__device__ bf16 g_Wo_hi[512 * 1024];
__device__ bf16 g_Wo_lo[512 * 1024];
__device__ bf16 g_x_hi[B_SZ * FEAT];
__device__ bf16 g_x_lo[B_SZ * FEAT];
__device__ bf16 g_hA_hi[B_SZ * HID];
__device__ bf16 g_hA_lo[B_SZ * HID];
__device__ bf16 g_hB_hi[B_SZ * HID];
__device__ bf16 g_hB_lo[B_SZ * HID];
__device__ float g_c[B_SZ * HID];

// ---------------- helpers -----------------------------------------------------
__device__ __forceinline__ uint32_t s2u(const void* p) {
    uint32_t a;
    asm("{.reg .u64 t; cvta.to.shared.u64 t,%1; cvt.u32.u64 %0,t;}" : "=r"(a) : "l"(p));
    return a;
}
#define CP16(dst, src) asm volatile("cp.async.cg.shared.global [%0], [%1], 16;" ::"r"(dst), "l"(src))
#define CPCOMMIT() asm volatile("cp.async.commit_group;" ::: "memory")
#define CPWAIT1() asm volatile("cp.async.wait_group 1;" ::: "memory")

__device__ __forceinline__ void ldsm4(uint32_t* r, uint32_t a) {
    asm volatile("ldmatrix.sync.aligned.m8n8.x4.shared.b16 {%0,%1,%2,%3},[%4];"
                 : "=r"(r[0]), "=r"(r[1]), "=r"(r[2]), "=r"(r[3]) : "r"(a));
}
__device__ __forceinline__ void mma16816(float* c, const uint32_t* a, const uint32_t* b) {
    asm volatile("mma.sync.aligned.m16n8k16.row.col.f32.bf16.bf16.f32 "
                 "{%0,%1,%2,%3},{%4,%5,%6,%7},{%8,%9},{%0,%1,%2,%3};"
                 : "+f"(c[0]), "+f"(c[1]), "+f"(c[2]), "+f"(c[3])
                 : "r"(a[0]), "r"(a[1]), "r"(a[2]), "r"(a[3]), "r"(b[0]), "r"(b[1]));
}

__device__ __forceinline__ float sig_(float x) { return 1.f / (1.f + __expf(-x)); }
__device__ __forceinline__ float tanh_(float x) { return 2.f * sig_(2.f * x) - 1.f; }
__device__ __forceinline__ float sp_(float x) { return fmaxf(x, 0.f) + __logf(1.f + __expf(-fabsf(x))); }
__device__ __forceinline__ void splt(float v, bf16& h, bf16& l) {
    h = __float2bfloat16(v); l = __float2bfloat16(v - __bfloat162float(h));
}

// ---------------- swizzled smem addressing ------------------------------------
__device__ __forceinline__ uint32_t swz(int row, int col16) {
    return (uint32_t)(row * 64 + ((col16 ^ (row & 3)) << 4));
}

// gates stage: AH | AL | BH | BL, each 128 rows x 64B
#define G_AL 8192
#define G_BH 16384
#define G_BL 24576
#define G_STG 32768
#define G_BIAS (3 * G_STG)
#define G_SMEM (G_BIAS + 1024)              // 2 CTAs/SM

// heads stage: AH | AL (64 rows), BH | BL (128 rows)
#define H_AL 4096
#define H_BH 8192
#define H_BL 16384
#define H_STG 24576
#define H_BIAS (3 * H_STG)
#define H_SMEM (H_BIAS + 512)               // 3 CTAs/SM

// ---------------- loaders (swizzled) -------------------------------------------
__device__ __forceinline__ void g_load(uint32_t stg,
                                       const bf16* __restrict__ aH, const bf16* __restrict__ aL, int aK,
                                       const bf16* __restrict__ bH, const bf16* __restrict__ bL, int bK,
                                       int tid) {
#pragma unroll
    for (int q = 0; q < 2; ++q) {
        const int idx = tid + q * 256;
        const int r = idx >> 2, c = idx & 3;
        const uint32_t d = swz(r, c);
        CP16(stg + d,        (const char*)(aH + (size_t)r * aK) + c * 16);
        CP16(stg + G_AL + d, (const char*)(aL + (size_t)r * aK) + c * 16);
        CP16(stg + G_BH + d, (const char*)(bH + (size_t)r * bK) + c * 16);
        CP16(stg + G_BL + d, (const char*)(bL + (size_t)r * bK) + c * 16);
    }
    CPCOMMIT();
}
__device__ __forceinline__ void h_load(uint32_t stg,
                                       const bf16* __restrict__ aH, const bf16* __restrict__ aL,
                                       const bf16* __restrict__ bH, const bf16* __restrict__ bL,
                                       int tid) {
#pragma unroll
    for (int q = 0; q < 2; ++q) {
        const int idx = tid + q * 128;
        const int r = idx >> 2, c = idx & 3;
        const uint32_t d = swz(r, c);
        CP16(stg + d,        (const char*)(aH + (size_t)r * HID) + c * 16);
        CP16(stg + H_AL + d, (const char*)(aL + (size_t)r * HID) + c * 16);
    }
#pragma unroll
    for (int q = 0; q < 4; ++q) {
        const int idx = tid + q * 128;
        const int r = idx >> 2, c = idx & 3;
        const uint32_t d = swz(r, c);
        CP16(stg + H_BH + d, (const char*)(bH + (size_t)r * 1024) + c * 16);
        CP16(stg + H_BL + d, (const char*)(bL + (size_t)r * 1024) + c * 16);
    }
    CPCOMMIT();
}

// ---------------- compute one fused k32 chunk; warp tile 32x64 ------------------
template <int ALO, int BHI, int BLO>
__device__ __forceinline__ void compute_chunk(uint32_t sa, float acc[2][8][4],
                                              int wm, int wn, int lane) {
#pragma unroll
    for (int kk = 0; kk < 2; ++kk) {
        uint32_t ahi[2][4], alo[2][4];
        const int acol = kk * 2 + (lane >> 4);
#pragma unroll
        for (int i = 0; i < 2; ++i) {
            const int row = wm * 32 + i * 16 + (lane & 15);
            ldsm4(ahi[i], sa + swz(row, acol));
            ldsm4(alo[i], sa + ALO + swz(row, acol));
        }
        const int bcol = kk * 2 + ((lane >> 3) & 1);
#pragma unroll
        for (int jp = 0; jp < 4; ++jp) {
            const int brow = wn * 64 + jp * 16 + ((lane & 7) | ((lane >> 4) << 3));
            uint32_t bh[4], bl[4];
            ldsm4(bh, sa + BHI + swz(brow, bcol));
#pragma unroll
            for (int i = 0; i < 2; ++i) {
                mma16816(acc[i][jp * 2 + 0], ahi[i], &bh[0]);
                mma16816(acc[i][jp * 2 + 1], ahi[i], &bh[2]);
            }
            ldsm4(bl, sa + BLO + swz(brow, bcol));
#pragma unroll
            for (int i = 0; i < 2; ++i) {
                mma16816(acc[i][jp * 2 + 0], alo[i], &bh[0]);
                mma16816(acc[i][jp * 2 + 1], alo[i], &bh[2]);
            }
#pragma unroll
            for (int i = 0; i < 2; ++i) {
                mma16816(acc[i][jp * 2 + 0], ahi[i], &bl[0]);
                mma16816(acc[i][jp * 2 + 1], ahi[i], &bl[2]);
            }
        }
    }
}

// ---------------- weight repack (coalescing permutation) ------------------------
__global__ void conv_weights(const float* __restrict__ Wih, const float* __restrict__ Whh,
                             const float* __restrict__ Wmu, const float* __restrict__ Wsp) {
    int i = blockIdx.x * 256 + threadIdx.x;
    const int NG = 4096 * 1280;
    if (i < NG) {
        int r = i / 1280, k = i - r * 1280;
        int ny = r >> 7, n = r & 127;
        int wn = n >> 6, gate = (n >> 4) & 3, hcg = (n >> 3) & 1, lq = (n >> 1) & 3, cb = n & 1;
        int hidden = ny * 32 + wn * 16 + lq * 4 + cb * 2 + hcg;
        int o = gate * HID + hidden;
        float v = (k < FEAT) ? Wih[(size_t)o * FEAT + k] : Whh[(size_t)o * HID + (k - FEAT)];
        splt(v, g_Wg_hi[i], g_Wg_lo[i]);
    } else {
        int j = i - NG;
        if (j < 512 * 1024) {
            int r = j / 1024, k = j - r * 1024;
            int nb = r >> 7, n = r & 127;
            int wn = n >> 6, jp = (n >> 4) & 3, head = (n >> 3) & 1, lq = (n >> 1) & 3, cb = n & 1;
            int f = nb * 64 + wn * 32 + lq * 8 + cb * 4 + jp;
            float v = head ? Wsp[(size_t)f * HID + k] : Wmu[(size_t)f * HID + k];
            splt(v, g_Wo_hi[j], g_Wo_lo[j]);
        }
    }
}

// ---------------- encoder (SIMT fp32) ----------------------------------------------
__global__ void __launch_bounds__(256, 2) enc_kernel(const float* __restrict__ S,
                                                     const float* __restrict__ We,
                                                     const float* __restrict__ be) {
    __shared__ float As[16 * 65], Ws[16 * 33];
    const int tid = threadIdx.x, tx = tid & 15, ty = tid >> 4;
    const int m0 = blockIdx.x * 64, n0 = blockIdx.y * 32;
    float acc[8];
#pragma unroll
    for (int i = 0; i < 8; ++i) acc[i] = 0.f;
    const int rl = tid >> 2, kl = (tid & 3) * 4;
    for (int k0 = 0; k0 < SCENE; k0 += 16) {
        float4 v = *reinterpret_cast<const float4*>(&S[(size_t)(m0 + rl) * SCENE + k0 + kl]);
        As[(kl + 0) * 65 + rl] = v.x; As[(kl + 1) * 65 + rl] = v.y;
        As[(kl + 2) * 65 + rl] = v.z; As[(kl + 3) * 65 + rl] = v.w;
        if (tid < 128) {
            int c = tid >> 2, kc = (tid & 3) * 4;
            float4 w = *reinterpret_cast<const float4*>(&We[(size_t)(n0 + c) * SCENE + k0 + kc]);
            Ws[(kc + 0) * 33 + c] = w.x; Ws[(kc + 1) * 33 + c] = w.y;
            Ws[(kc + 2) * 33 + c] = w.z; Ws[(kc + 3) * 33 + c] = w.w;
        }
        __syncthreads();
#pragma unroll
        for (int k = 0; k < 16; ++k) {
            float a0 = As[k * 65 + ty * 4], a1 = As[k * 65 + ty * 4 + 1];
            float a2 = As[k * 65 + ty * 4 + 2], a3 = As[k * 65 + ty * 4 + 3];
            float w0 = Ws[k * 33 + tx * 2], w1 = Ws[k * 33 + tx * 2 + 1];
            acc[0] = fmaf(a0, w0, acc[0]); acc[1] = fmaf(a0, w1, acc[1]);
            acc[2] = fmaf(a1, w0, acc[2]); acc[3] = fmaf(a1, w1, acc[3]);
            acc[4] = fmaf(a2, w0, acc[4]); acc[5] = fmaf(a2, w1, acc[5]);
            acc[6] = fmaf(a3, w0, acc[6]); acc[7] = fmaf(a3, w1, acc[7]);
        }
        __syncthreads();
    }
#pragma unroll
    for (int c = 0; c < 2; ++c) {
        const int col = n0 + tx * 2 + c;
        const float b = be[col];
#pragma unroll
        for (int r = 0; r < 4; ++r) {
            const int row = m0 + ty * 4 + r;
            float v = acc[r * 2 + c] + b;
            v = 0.5f * v * (1.f + erff(v * 0.7071067811865476f));
            splt(v, g_x_hi[(size_t)row * FEAT + col], g_x_lo[(size_t)row * FEAT + col]);
        }
    }
}

// ---------------- gates GEMM + in-register LSTM cell -------------------------------
// CTA 128x128, 256 threads, 8 warps: wm = wid>>1, wn = wid&1
template <bool FIRST>
__global__ void __launch_bounds__(256, 2) gates_mma(int t, const float* __restrict__ bih,
                                                    const float* __restrict__ bhh) {
    extern __shared__ char sm[];
    const uint32_t smu = s2u(sm);
    const int tid = threadIdx.x, lane = tid & 31, wid = tid >> 5;
    const int wm = wid >> 1, wn = wid & 1;
    const int m0 = blockIdx.x * 128, ny = blockIdx.y;

    const bf16* hp_hi = (t & 1) ? g_hA_hi : g_hB_hi;
    const bf16* hp_lo = (t & 1) ? g_hA_lo : g_hB_lo;
    bf16* ho_hi = (t & 1) ? g_hB_hi : g_hA_hi;
    bf16* ho_lo = (t & 1) ? g_hB_lo : g_hA_lo;

    float* bs = reinterpret_cast<float*>(sm + G_BIAS);
    if (tid < 128) {
        // bs[wn*64 + gate*16 + hl], hl = lq*4 + cb*2 + hcg
        int wn2 = tid >> 6, gate = (tid >> 4) & 3, hl = tid & 15;
        int hidden = ny * 32 + wn2 * 16 + hl;
        bs[tid] = bih[gate * HID + hidden] + bhh[gate * HID + hidden];
    }

    const int NC = FIRST ? 8 : 40;
    float acc[2][8][4];
#pragma unroll
    for (int i = 0; i < 2; ++i)
#pragma unroll
        for (int j = 0; j < 8; ++j)
#pragma unroll
            for (int e = 0; e < 4; ++e) acc[i][j][e] = 0.f;

    auto issue_load = [&](int cs) {
        const int kc = cs * 32;
        const bf16 *aH, *aL; int aK;
        if (FIRST || kc < 256) {
            aH = g_x_hi + (size_t)m0 * FEAT + kc;
            aL = g_x_lo + (size_t)m0 * FEAT + kc; aK = FEAT;
        } else {
            aH = hp_hi + (size_t)m0 * HID + (kc - 256);
            aL = hp_lo + (size_t)m0 * HID + (kc - 256); aK = HID;
        }
        const size_t bo = (size_t)(ny * 128) * 1280 + kc;
        g_load(smu + (cs % 3) * G_STG, aH, aL, aK, g_Wg_hi + bo, g_Wg_lo + bo, 1280, tid);
    };

    issue_load(0); issue_load(1);
    for (int cs = 0; cs < NC; ++cs) {
        CPWAIT1();
        __syncthreads();
        compute_chunk<G_AL, G_BH, G_BL>(smu + (cs % 3) * G_STG, acc, wm, wn, lane);
        if (cs + 2 < NC) issue_load(cs + 2); else CPCOMMIT();
    }

    // coalesced in-register LSTM cell epilogue
    // acc[i][gate*2+hcg][rp*2+cb] -> hidden = ny*32 + wn*16 + lq*4 + cb*2 + hcg
    const int lane4 = lane >> 2, lq = lane & 3;
#pragma unroll
    for (int i = 0; i < 2; ++i)
#pragma unroll
        for (int rp = 0; rp < 2; ++rp) {
            const int row = m0 + wm * 32 + i * 16 + lane4 + rp * 8;
            const size_t base = (size_t)row * HID + ny * 32 + wn * 16 + lq * 4;
            float4 cold = make_float4(0.f, 0.f, 0.f, 0.f);
            if (!FIRST) cold = *reinterpret_cast<const float4*>(&g_c[base]);
            float cn[4];
            union { bf16 b[4]; uint2 u; } Hh, Hl;
#pragma unroll
            for (int v = 0; v < 4; ++v) {
                const int cb = v >> 1, hcg = v & 1;
                const int e = rp * 2 + cb;
                const int bb = wn * 64 + lq * 4 + v;
                const float gi = acc[i][0 + hcg][e] + bs[bb + 0];
                const float gf = acc[i][2 + hcg][e] + bs[bb + 16];
                const float gg = acc[i][4 + hcg][e] + bs[bb + 32];
                const float go = acc[i][6 + hcg][e] + bs[bb + 48];
                const float cp = FIRST ? 0.f : ((const float*)&cold)[v];
                const float c2 = sig_(gf) * cp + sig_(gi) * tanh_(gg);
                cn[v] = c2;
                splt(sig_(go) * tanh_(c2), Hh.b[v], Hl.b[v]);
            }
            *reinterpret_cast<float4*>(&g_c[base]) = *reinterpret_cast<float4*>(cn);
            *reinterpret_cast<uint2*>(&ho_hi[base]) = Hh.u;
            *reinterpret_cast<uint2*>(&ho_lo[base]) = Hl.u;
        }
}

// ---------------- heads GEMM: mu | softplus sigma | z -------------------------------
// CTA 64x128, 128 threads, 4 warps: wm = wid>>1, wn = wid&1
__global__ void __launch_bounds__(128, 3) heads_mma(int t, const float* __restrict__ bmu,
                                                    const float* __restrict__ bsp,
                                                    const float* __restrict__ eps,
                                                    float* __restrict__ zs,
                                                    float* __restrict__ mus,
                                                    float* __restrict__ sgs) {
    extern __shared__ char sm[];
    const uint32_t smu = s2u(sm);
    const int tid = threadIdx.x, lane = tid & 31, wid = tid >> 5;
    const int wm = wid >> 1, wn = wid & 1;
    const int m0 = blockIdx.x * 64, nb = blockIdx.y;

    const bf16* hc_hi = (t & 1) ? g_hB_hi : g_hA_hi;
    const bf16* hc_lo = (t & 1) ? g_hB_lo : g_hA_lo;

    float* bs = reinterpret_cast<float*>(sm + H_BIAS);
    {
        // bs[wn*64 + head*32 + fl], fl = lq*8 + cb*4 + jp
        int wn2 = tid >> 6, head = (tid >> 5) & 1, fl = tid & 31;
        int f = nb * 64 + wn2 * 32 + fl;
        bs[tid] = head ? bsp[f] : bmu[f];
    }

    const int NC = 32;
    float acc[2][8][4];
#pragma unroll
    for (int i = 0; i < 2; ++i)
#pragma unroll
        for (int j = 0; j < 8; ++j)
#pragma unroll
            for (int e = 0; e < 4; ++e) acc[i][j][e] = 0.f;

    auto issue_load = [&](int cs) {
        const int kc = cs * 32;
        const size_t bo = (size_t)(nb * 128) * 1024 + kc;
        h_load(smu + (cs % 3) * H_STG,
               hc_hi + (size_t)m0 * HID + kc, hc_lo + (size_t)m0 * HID + kc,
               g_Wo_hi + bo, g_Wo_lo + bo, tid);
    };

    issue_load(0); issue_load(1);
    for (int cs = 0; cs < NC; ++cs) {
        CPWAIT1();
        __syncthreads();
        compute_chunk<H_AL, H_BH, H_BL>(smu + (cs % 3) * H_STG, acc, wm, wn, lane);
        if (cs + 2 < NC) issue_load(cs + 2); else CPCOMMIT();
    }

    // coalesced heads epilogue:
    // mu: acc[i][jp*2+0], sigma: acc[i][jp*2+1]; f = nb*64 + wn*32 + lq*8 + cb*4 + jp
    const int lane4 = lane >> 2, lq = lane & 3;
#pragma unroll
    for (int i = 0; i < 2; ++i)
#pragma unroll
        for (int rp = 0; rp < 2; ++rp) {
            const int row = m0 + wm * 32 + i * 16 + lane4 + rp * 8;
#pragma unroll
            for (int cb = 0; cb < 2; ++cb) {
                const int e = rp * 2 + cb;
                const int flb = lq * 8 + cb * 4;
                const size_t o = (size_t)t * B_SZ * FEAT + (size_t)row * FEAT
                                 + nb * 64 + wn * 32 + flb;
                const size_t xb = (size_t)row * FEAT + nb * 64 + wn * 32 + flb;
                const float4 ev = *reinterpret_cast<const float4*>(&eps[o]);
                float zv[4], mv[4], sv[4];
                union { bf16 b[4]; uint2 u; } Zh, Zl;
#pragma unroll
                for (int jp = 0; jp < 4; ++jp) {
                    const float mu = acc[i][jp * 2 + 0][e] + bs[wn * 64 + flb + jp];
                    const float sg = sp_(acc[i][jp * 2 + 1][e] + bs[wn * 64 + 32 + flb + jp]);
                    const float z = mu + sg * ((const float*)&ev)[jp];
                    mv[jp] = mu; sv[jp] = sg; zv[jp] = z;
                    splt(z, Zh.b[jp], Zl.b[jp]);
                }
                *reinterpret_cast<float4*>(&zs[o])  = *reinterpret_cast<float4*>(zv);
                *reinterpret_cast<float4*>(&mus[o]) = *reinterpret_cast<float4*>(mv);
                *reinterpret_cast<float4*>(&sgs[o]) = *reinterpret_cast<float4*>(sv);
                *reinterpret_cast<uint2*>(&g_x_hi[xb]) = Zh.u;
                *reinterpret_cast<uint2*>(&g_x_lo[xb]) = Zl.u;
            }
        }
}

// ---------------- launch --------------------------------------------------------------
extern "C" void kernel_launch(void* const* d_in, const int* in_sizes, int n_in,
                              void* d_out, int out_size) {
    (void)in_sizes; (void)n_in; (void)out_size;
    const float* S   = (const float*)d_in[0];
    const float* eps = (const float*)d_in[1];
    const float* We  = (const float*)d_in[3];
    const float* be  = (const float*)d_in[4];
    const float* Wih = (const float*)d_in[5];
    const float* Whh = (const float*)d_in[6];
    const float* bih = (const float*)d_in[7];
    const float* bhh = (const float*)d_in[8];
    const float* Wmu = (const float*)d_in[9];
    const float* bmu = (const float*)d_in[10];
    const float* Wsp = (const float*)d_in[11];
    const float* bsp = (const float*)d_in[12];

    float* out = (float*)d_out;
    const size_t slab = (size_t)NSLOTS * B_SZ * FEAT;
    float *zs = out, *mus = out + slab, *sgs = out + 2 * slab;

    static bool attr_done = false;
    if (!attr_done) {
        cudaFuncSetAttribute(gates_mma<true>,  cudaFuncAttributeMaxDynamicSharedMemorySize, G_SMEM);
        cudaFuncSetAttribute(gates_mma<false>, cudaFuncAttributeMaxDynamicSharedMemorySize, G_SMEM);
        cudaFuncSetAttribute(heads_mma,        cudaFuncAttributeMaxDynamicSharedMemorySize, H_SMEM);
        attr_done = true;
    }

    conv_weights<<<22528, 256>>>(Wih, Whh, Wmu, Wsp);
    enc_kernel<<<dim3(B_SZ / 64, FEAT / 32), 256>>>(S, We, be);

    for (int t = 0; t < NSLOTS; ++t) {
        if (t == 0)
            gates_mma<true><<<dim3(B_SZ / 128, 32), 256, G_SMEM>>>(t, bih, bhh);
        else
            gates_mma<false><<<dim3(B_SZ / 128, 32), 256, G_SMEM>>>(t, bih, bhh);
        heads_mma<<<dim3(B_SZ / 64, 4), 128, H_SMEM>>>(t, bmu, bsp, eps, zs, mus, sgs);
    }
}